// round 5
// baseline (speedup 1.0000x reference)
#include <cuda_runtime.h>

#define N_PIX 4096
#define M_PIX 1024

typedef unsigned long long u64;

// packed f32x2 helpers (sm_103a FFMA2 — only reachable via PTX)
#define FMA2(acc, a, b) \
    asm("fma.rn.f32x2 %0, %1, %2, %0;" : "+l"(acc) : "l"(a), "l"(b))
#define ADD2(d, a, b) \
    asm("add.rn.f32x2 %0, %1, %2;" : "=l"(d) : "l"(a), "l"(b))
#define SPLAT2(d, f) \
    asm("mov.b64 %0, {%1, %1};" : "=l"(d) : "r"(__float_as_uint(f)))

__device__ __forceinline__ float unpack_sum(u64 v) {
    float2 f = *(float2*)&v;
    return f.x + f.y;
}

// Scratch (device globals — no allocation allowed)
__device__ __align__(16) float g_q[16 * 16 * N_PIX];   // [b][16][n]
__device__ __align__(16) float g_k[16 * 16 * M_PIX];   // [b][16][m]
__device__ __align__(16) float g_v[16 * 64 * M_PIX];   // [b][64][m]

// ---------------------------------------------------------------------------
// Kernel 1: q/k/v 1x1-conv + 2x2 maxpool. 128 threads = 128 pixels = 2 rows.
// Weights transposed in smem: sWt[c][o] (stride 100) so output-pairs are
// adjacent -> broadcast LDS.128 feeds 2 FMA2 = 4 element-FMAs.
// o order: 0-15 wq, 16-31 wk, 32-95 wv.
// ---------------------------------------------------------------------------
__global__ __launch_bounds__(128) void proj_pool_kernel(
    const float* __restrict__ x,
    const float* __restrict__ wq,
    const float* __restrict__ wk,
    const float* __restrict__ wv)
{
    extern __shared__ float sm[];
    float* sWt = sm;                 // 128 * 100 = 12800
    float* kb  = sm + 12800;         // 128 * 17
    float* vb  = kb + 128 * 17;      // 128 * 65

    const int t = threadIdx.x;
    for (int i = t; i < 12288; i += 128) {
        int o = i >> 7, c = i & 127;
        float wv_;
        if (o < 16)      wv_ = wq[i];
        else if (o < 32) wv_ = wk[i - 2048];
        else             wv_ = wv[i - 4096];
        sWt[c * 100 + o] = wv_;
    }
    __syncthreads();

    const int b = blockIdx.y;
    const int n = blockIdx.x * 128 + t;
    const float* xb = x + (size_t)b * 128 * N_PIX;

    u64 a2[48];
#pragma unroll
    for (int j = 0; j < 48; j++) a2[j] = 0ull;

#pragma unroll 4
    for (int c = 0; c < 128; c++) {
        float xv = xb[c * N_PIX + n];
        u64 xs; SPLAT2(xs, xv);
        const ulonglong2* wrow = (const ulonglong2*)&sWt[c * 100];
#pragma unroll
        for (int jj = 0; jj < 24; jj++) {
            ulonglong2 w2 = wrow[jj];
            FMA2(a2[jj * 2],     xs, w2.x);
            FMA2(a2[jj * 2 + 1], xs, w2.y);
        }
    }

    // q: o = 0..15  (a2[0..7])
#pragma unroll
    for (int j = 0; j < 8; j++) {
        float2 f = *(float2*)&a2[j];
        g_q[(b * 16 + 2 * j)     * N_PIX + n] = f.x;
        g_q[(b * 16 + 2 * j + 1) * N_PIX + n] = f.y;
    }
    // k: o = 16..31 (a2[8..15]) -> kb ; v: o = 32..95 (a2[16..47]) -> vb
#pragma unroll
    for (int j = 0; j < 8; j++) {
        float2 f = *(float2*)&a2[8 + j];
        kb[t * 17 + 2 * j]     = f.x;
        kb[t * 17 + 2 * j + 1] = f.y;
    }
#pragma unroll
    for (int j = 0; j < 32; j++) {
        float2 f = *(float2*)&a2[16 + j];
        vb[t * 65 + 2 * j]     = f.x;
        vb[t * 65 + 2 * j + 1] = f.y;
    }
    __syncthreads();

    const int mbase = blockIdx.x * 32;
    for (int idx = t; idx < 2560; idx += 128) {
        int ch = idx >> 5, wp = idx & 31;
        int t00 = wp * 2, t01 = t00 + 1, t10 = t00 + 64, t11 = t00 + 65;
        if (ch < 16) {
            float r = fmaxf(fmaxf(kb[t00 * 17 + ch], kb[t01 * 17 + ch]),
                            fmaxf(kb[t10 * 17 + ch], kb[t11 * 17 + ch]));
            g_k[((b * 16 + ch) << 10) + mbase + wp] = r;
        } else {
            int c2 = ch - 16;
            float r = fmaxf(fmaxf(vb[t00 * 65 + c2], vb[t01 * 65 + c2]),
                            fmaxf(vb[t10 * 65 + c2], vb[t11 * 65 + c2]));
            g_v[((b * 64 + c2) << 10) + mbase + wp] = r;
        }
    }
}

// ---------------------------------------------------------------------------
// Kernel 2: fused attention, flash-style m-chunked, f32x2-packed along m.
// 256 threads, 2 CTAs/SM. SMEM identical to R4 (62.3KB).
// GEMM: warp owns c0=w*8; lane: ngrp=lane&7 (n=ngrp+8j, j<4),
//       msplit=lane>>3 (32-m window). acc2[8][4] packed (even m, odd m).
// ---------------------------------------------------------------------------
__global__ __launch_bounds__(256, 2) void attn_kernel(
    const float* __restrict__ x,
    const float* __restrict__ wo,
    const float* __restrict__ gamma,
    float* __restrict__ out)
{
    extern __shared__ float sm[];
    float* sV   = sm;                 // 64*132 = 8448
    float* sK   = sV + 8448;          // 16*132 = 2112
    float* sP   = sK + 2112;          // 32*132 = 4224
    float* sQ   = sP + 4224;          // 512
    float* sSum = sQ + 512;           // 32*9 = 288

    const int t    = threadIdx.x;
    const int w    = t >> 5;          // warp 0..7
    const int lane = t & 31;
    const int b    = blockIdx.y;
    const int n0   = blockIdx.x * 32;

    const int sN     = lane;          // S-phase: n = lane, m-window = w*16
    const int c0     = w * 8;         // GEMM warp c-range
    const int ngrp   = lane & 7;      // GEMM: n = ngrp + 8j
    const int msplit = lane >> 3;     // GEMM: 32-m window within chunk

    for (int i = t; i < 512; i += 256) {
        int d = i >> 5, j = i & 31;
        sQ[i] = g_q[(b * 16 + d) * N_PIX + n0 + j];
    }

    u64 acc2[8][4];
#pragma unroll
    for (int i = 0; i < 8; i++)
#pragma unroll
        for (int j = 0; j < 4; j++) acc2[i][j] = 0ull;
    float rowsum = 0.f;

    const float4* gk4 = (const float4*)(g_k + b * 16 * M_PIX);
    const float4* gv4 = (const float4*)(g_v + b * 64 * M_PIX);
    float4* sK4 = (float4*)sK;
    float4* sV4 = (float4*)sV;

    for (int chk = 0; chk < 8; chk++) {
        __syncthreads();   // previous chunk fully consumed (covers sQ on chk=0)

        // ---- stage K chunk [16][128] and V chunk [64][128] ----
#pragma unroll
        for (int q = 0; q < 2; q++) {
            int i = t + q * 256;
            int r = i >> 5, c = i & 31;
            sK4[r * 33 + c] = gk4[r * 256 + chk * 32 + c];
        }
#pragma unroll
        for (int q = 0; q < 8; q++) {
            int i = t + q * 256;
            int r = i >> 5, c = i & 31;
            sV4[r * 33 + c] = gv4[r * 256 + chk * 32 + c];
        }
        __syncthreads();

        // ---- S-chunk: n=sN, m in [w*16, w*16+16); packed over m-pairs ----
        {
            u64 sa2[8];
#pragma unroll
            for (int k = 0; k < 8; k++) sa2[k] = 0ull;
#pragma unroll
            for (int d = 0; d < 16; d++) {
                u64 qs; SPLAT2(qs, sQ[d * 32 + sN]);
#pragma unroll
                for (int k = 0; k < 4; k++) {
                    ulonglong2 kv = *(const ulonglong2*)&sK[d * 132 + w * 16 + k * 4];
                    FMA2(sa2[k * 2],     qs, kv.x);
                    FMA2(sa2[k * 2 + 1], qs, kv.y);
                }
            }
#pragma unroll
            for (int k = 0; k < 4; k++) {
                float2 e0 = *(float2*)&sa2[k * 2];
                float2 e1 = *(float2*)&sa2[k * 2 + 1];
                float4 v;
                v.x = __expf(e0.x); v.y = __expf(e0.y);
                v.z = __expf(e1.x); v.w = __expf(e1.y);
                rowsum += v.x + v.y + v.z + v.w;
                *(float4*)&sP[sN * 132 + w * 16 + k * 4] = v;
            }
        }
        __syncthreads();

        // ---- GEMM chunk: acc2[c][n] += V[c][m] * P[n][m] (packed m-pairs) ----
        {
            const float* pBase = sP + ngrp * 132 + msplit * 32;
            const float* vBase = sV + c0 * 132 + msplit * 32;
#pragma unroll
            for (int mm = 0; mm < 32; mm += 4) {
                ulonglong2 p2[4];
#pragma unroll
                for (int j = 0; j < 4; j++)
                    p2[j] = *(const ulonglong2*)(pBase + j * 8 * 132 + mm);
#pragma unroll
                for (int i = 0; i < 8; i++) {
                    ulonglong2 v2 = *(const ulonglong2*)(vBase + i * 132 + mm);
#pragma unroll
                    for (int j = 0; j < 4; j++) {
                        FMA2(acc2[i][j], v2.x, p2[j].x);
                        FMA2(acc2[i][j], v2.y, p2[j].y);
                    }
                }
            }
        }
    }

    sSum[sN * 9 + w] = rowsum;
    __syncthreads();   // all GEMM reads of sP/sV done

    // ---- reduce 4 m-splits (xor 8,16) then unpack even/odd m ----
    float* sO = sP;       // 64 x 33, aliases sP
    {
#pragma unroll
        for (int i = 0; i < 8; i++)
#pragma unroll
            for (int j = 0; j < 4; j++) {
                u64 v = acc2[i][j];
                u64 o1 = __shfl_xor_sync(0xffffffffu, v, 8);
                ADD2(v, v, o1);
                u64 o2 = __shfl_xor_sync(0xffffffffu, v, 16);
                ADD2(v, v, o2);
                acc2[i][j] = v;
            }
        if (msplit == 0) {
#pragma unroll
            for (int i = 0; i < 8; i++)
#pragma unroll
                for (int j = 0; j < 4; j++)
                    sO[(c0 + i) * 33 + ngrp + 8 * j] = unpack_sum(acc2[i][j]);
        }
    }
    // stage wo as sWo[c][o] (aliases sV region)
    float* sWo = sV;      // 64 x 132
    for (int i = t; i < 8192; i += 256) {
        int o = i >> 6, c = i & 63;
        sWo[c * 132 + o] = wo[i];
    }
    __syncthreads();

    // ---- Phase 3: out[o][n] = gamma*inv[n]*sum_c wo[o][c]*o_raw[c][n] + x ----
    {
        float inv = 0.f;
#pragma unroll
        for (int r = 0; r < 8; r++) inv += sSum[lane * 9 + r];
        inv = 1.f / inv;

        u64 oa2[8];
#pragma unroll
        for (int k = 0; k < 8; k++) oa2[k] = 0ull;
#pragma unroll 4
        for (int c = 0; c < 64; c++) {
            u64 os; SPLAT2(os, sO[c * 33 + lane]);
            const ulonglong2* w2 = (const ulonglong2*)&sWo[c * 132 + w * 16];
#pragma unroll
            for (int q4 = 0; q4 < 4; q4++) {
                ulonglong2 wv_ = w2[q4];
                FMA2(oa2[q4 * 2],     os, wv_.x);
                FMA2(oa2[q4 * 2 + 1], os, wv_.y);
            }
        }
        const float gsc = gamma[0] * inv;
        const size_t base = (size_t)(b * 128) * N_PIX + n0 + lane;
#pragma unroll
        for (int k = 0; k < 8; k++) {
            float2 f = *(float2*)&oa2[k];
            size_t gi0 = base + (size_t)(w * 16 + 2 * k) * N_PIX;
            out[gi0]         = fmaf(gsc, f.x, x[gi0]);
            out[gi0 + N_PIX] = fmaf(gsc, f.y, x[gi0 + N_PIX]);
        }
    }
}

// ---------------------------------------------------------------------------
extern "C" void kernel_launch(void* const* d_in, const int* in_sizes, int n_in,
                              void* d_out, int out_size)
{
    const float* x     = (const float*)d_in[0];
    const float* wq    = (const float*)d_in[1];
    const float* wk    = (const float*)d_in[2];
    const float* wv    = (const float*)d_in[3];
    const float* wo    = (const float*)d_in[4];
    const float* gamma = (const float*)d_in[5];
    float* out = (float*)d_out;

    const int smem1 = (12800 + 128 * 17 + 128 * 65) * 4;           // 93184
    const int smem2 = (8448 + 2112 + 4224 + 512 + 288) * 4;        // 62336

    cudaFuncSetAttribute(proj_pool_kernel, cudaFuncAttributeMaxDynamicSharedMemorySize, smem1);
    cudaFuncSetAttribute(attn_kernel,      cudaFuncAttributeMaxDynamicSharedMemorySize, smem2);

    proj_pool_kernel<<<dim3(32, 16), 128, smem1>>>(x, wq, wk, wv);
    attn_kernel<<<dim3(128, 16), 256, smem2>>>(x, wo, gamma, out);
}

// round 7
// speedup vs baseline: 1.0069x; 1.0069x over previous
#include <cuda_runtime.h>
#include <cstdint>

#define N_PIX 4096
#define M_PIX 1024

// cp.async helpers (16B per op)
#define CPA(dst32, srcp) \
    asm volatile("cp.async.ca.shared.global [%0], [%1], 16;" :: "r"(dst32), "l"(srcp) : "memory")
#define CP_COMMIT() asm volatile("cp.async.commit_group;" ::: "memory")
#define CP_WAIT0()  asm volatile("cp.async.wait_group 0;" ::: "memory")

// Scratch (device globals — no allocation allowed)
__device__ __align__(16) float g_q[16 * 16 * N_PIX];   // [b][16][n]
__device__ __align__(16) float g_k[16 * 16 * M_PIX];   // [b][16][m]
__device__ __align__(16) float g_v[16 * 64 * M_PIX];   // [b][64][m]

// ---------------------------------------------------------------------------
// Kernel 1: q/k/v 1x1-conv + 2x2 maxpool. 128 threads = 128 pixels = 2 rows.
// Weights transposed in smem sWt[c][o] (stride 100, rows 16B-aligned) so each
// c-step is 24 broadcast LDS.128 + 96 FFMA (FFMA-bound instead of LDS-bound).
// o order: 0-15 wq, 16-31 wk, 32-95 wv.
// ---------------------------------------------------------------------------
__global__ __launch_bounds__(128) void proj_pool_kernel(
    const float* __restrict__ x,
    const float* __restrict__ wq,
    const float* __restrict__ wk,
    const float* __restrict__ wv)
{
    extern __shared__ float sm[];
    float* sWt = sm;                 // 128 * 100 = 12800
    float* kb  = sm + 12800;         // 128 * 17 = 2176
    float* vb  = kb + 2176;          // 128 * 65 = 8320

    const int t = threadIdx.x;
    for (int i = t; i < 12288; i += 128) {
        int o = i >> 7, c = i & 127;
        float wv_;
        if (o < 16)      wv_ = wq[i];
        else if (o < 32) wv_ = wk[i - 2048];
        else             wv_ = wv[i - 4096];
        sWt[c * 100 + o] = wv_;
    }
    __syncthreads();

    const int b = blockIdx.y;
    const int n = blockIdx.x * 128 + t;
    const float* xb = x + (size_t)b * 128 * N_PIX;

    float a[96];
#pragma unroll
    for (int o = 0; o < 96; o++) a[o] = 0.f;

#pragma unroll 4
    for (int c = 0; c < 128; c++) {
        float xv = xb[c * N_PIX + n];
        const float4* wrow = (const float4*)&sWt[c * 100];
#pragma unroll
        for (int jj = 0; jj < 24; jj++) {
            float4 w4 = wrow[jj];
            a[jj * 4 + 0] = fmaf(w4.x, xv, a[jj * 4 + 0]);
            a[jj * 4 + 1] = fmaf(w4.y, xv, a[jj * 4 + 1]);
            a[jj * 4 + 2] = fmaf(w4.z, xv, a[jj * 4 + 2]);
            a[jj * 4 + 3] = fmaf(w4.w, xv, a[jj * 4 + 3]);
        }
    }

#pragma unroll
    for (int o = 0; o < 16; o++) g_q[(b * 16 + o) * N_PIX + n] = a[o];
#pragma unroll
    for (int o = 0; o < 16; o++) kb[t * 17 + o] = a[16 + o];
#pragma unroll
    for (int o = 0; o < 64; o++) vb[t * 65 + o] = a[32 + o];
    __syncthreads();

    const int mbase = blockIdx.x * 32;
    for (int idx = t; idx < 2560; idx += 128) {
        int ch = idx >> 5, wp = idx & 31;
        int t00 = wp * 2, t01 = t00 + 1, t10 = t00 + 64, t11 = t00 + 65;
        if (ch < 16) {
            float r = fmaxf(fmaxf(kb[t00 * 17 + ch], kb[t01 * 17 + ch]),
                            fmaxf(kb[t10 * 17 + ch], kb[t11 * 17 + ch]));
            g_k[((b * 16 + ch) << 10) + mbase + wp] = r;
        } else {
            int c2 = ch - 16;
            float r = fmaxf(fmaxf(vb[t00 * 65 + c2], vb[t01 * 65 + c2]),
                            fmaxf(vb[t10 * 65 + c2], vb[t11 * 65 + c2]));
            g_v[((b * 64 + c2) << 10) + mbase + wp] = r;
        }
    }
}

// ---------------------------------------------------------------------------
// Kernel 2: fused attention, flash-style m-chunked (no row-max; scores are
// statistically bounded). 256 threads, 2 CTAs/SM.
// Double-buffered K/V staging via cp.async: copy of chunk c+1 overlaps the
// S-phase + GEMM of chunk c. 2 syncs per chunk.
// SMEM floats: sV[2]x8448, sK[2]x2112, sP 4224, sQ 512, sSum 288 = 104.6KB.
// ---------------------------------------------------------------------------
#define SV_OFF(buf)  ((buf) ? 8448u : 0u)
#define SK_OFF(buf)  (16896u + ((buf) ? 2112u : 0u))
#define SP_OFF       21120u
#define SQ_OFF       25344u
#define SSUM_OFF     25856u

__device__ __forceinline__ void stage_chunk(
    uint32_t sbase, int buf, int chk, int t,
    const float4* __restrict__ gk4, const float4* __restrict__ gv4)
{
    uint32_t kdst = sbase + SK_OFF(buf) * 4u;
    uint32_t vdst = sbase + SV_OFF(buf) * 4u;
#pragma unroll
    for (int q = 0; q < 2; q++) {
        int i = t + q * 256;
        int r = i >> 5, c = i & 31;
        CPA(kdst + (uint32_t)(r * 33 + c) * 16u, gk4 + r * 256 + chk * 32 + c);
    }
#pragma unroll
    for (int q = 0; q < 8; q++) {
        int i = t + q * 256;
        int r = i >> 5, c = i & 31;
        CPA(vdst + (uint32_t)(r * 33 + c) * 16u, gv4 + r * 256 + chk * 32 + c);
    }
}

__global__ __launch_bounds__(256, 2) void attn_kernel(
    const float* __restrict__ x,
    const float* __restrict__ wo,
    const float* __restrict__ gamma,
    float* __restrict__ out)
{
    extern __shared__ float sm[];
    float* sP   = sm + SP_OFF;        // 32*132
    float* sQ   = sm + SQ_OFF;        // 512
    float* sSum = sm + SSUM_OFF;      // 32*9

    const int t    = threadIdx.x;
    const int w    = t >> 5;          // warp 0..7
    const int lane = t & 31;
    const int b    = blockIdx.y;
    const int n0   = blockIdx.x * 32;

    const int sN     = lane;          // S-phase: n = lane, m-window = w*16
    const int c0     = w * 8;         // GEMM warp c-range
    const int ngrp   = lane & 3;      // GEMM: n = ngrp + 4j (j<8)
    const int msplit = lane >> 2;     // GEMM: 16-m window within chunk

    const uint32_t sbase = (uint32_t)__cvta_generic_to_shared(sm);
    const float4* gk4 = (const float4*)(g_k + b * 16 * M_PIX);
    const float4* gv4 = (const float4*)(g_v + b * 64 * M_PIX);

    // prologue: async-stage chunk 0, stage Q tile
    stage_chunk(sbase, 0, 0, t, gk4, gv4);
    CP_COMMIT();
    for (int i = t; i < 512; i += 256) {
        int d = i >> 5, j = i & 31;
        sQ[i] = g_q[(b * 16 + d) * N_PIX + n0 + j];
    }

    float acc[8][8];
#pragma unroll
    for (int i = 0; i < 8; i++)
#pragma unroll
        for (int j = 0; j < 8; j++) acc[i][j] = 0.f;
    float rowsum = 0.f;

    for (int chk = 0; chk < 8; chk++) {
        const int buf = chk & 1;
        const float* sK = sm + SK_OFF(buf);
        const float* sV = sm + SV_OFF(buf);

        CP_WAIT0();
        __syncthreads();   // chunk chk visible to all; all done with GEMM(chk-1)

        if (chk < 7) {
            stage_chunk(sbase, buf ^ 1, chk + 1, t, gk4, gv4);
            CP_COMMIT();
        }

        // ---- S-chunk: n=sN, m in [w*16, w*16+16); exp; rowsum ----
        {
            float4 sa[4];
#pragma unroll
            for (int k = 0; k < 4; k++) sa[k] = make_float4(0.f, 0.f, 0.f, 0.f);
#pragma unroll
            for (int d = 0; d < 16; d++) {
                float qv = sQ[d * 32 + sN];
#pragma unroll
                for (int k = 0; k < 4; k++) {
                    float4 kv = *(const float4*)&sK[d * 132 + w * 16 + k * 4];
                    sa[k].x = fmaf(qv, kv.x, sa[k].x);
                    sa[k].y = fmaf(qv, kv.y, sa[k].y);
                    sa[k].z = fmaf(qv, kv.z, sa[k].z);
                    sa[k].w = fmaf(qv, kv.w, sa[k].w);
                }
            }
#pragma unroll
            for (int k = 0; k < 4; k++) {
                sa[k].x = __expf(sa[k].x);
                sa[k].y = __expf(sa[k].y);
                sa[k].z = __expf(sa[k].z);
                sa[k].w = __expf(sa[k].w);
                rowsum += sa[k].x + sa[k].y + sa[k].z + sa[k].w;
                *(float4*)&sP[sN * 132 + w * 16 + k * 4] = sa[k];
            }
        }
        __syncthreads();

        // ---- GEMM chunk: acc[c][n] += V[c][m]*P[n][m], m in msplit window ----
        {
            const float* pBase = sP + ngrp * 132 + msplit * 16;
            const float* vBase = sV + c0 * 132 + msplit * 16;
#pragma unroll
            for (int mm = 0; mm < 16; mm += 4) {
                float4 p[8];
#pragma unroll
                for (int j = 0; j < 8; j++)
                    p[j] = *(const float4*)(pBase + j * 4 * 132 + mm);
#pragma unroll
                for (int i = 0; i < 8; i++) {
                    float4 v = *(const float4*)(vBase + i * 132 + mm);
#pragma unroll
                    for (int j = 0; j < 8; j++) {
                        acc[i][j] = fmaf(v.x, p[j].x, acc[i][j]);
                        acc[i][j] = fmaf(v.y, p[j].y, acc[i][j]);
                        acc[i][j] = fmaf(v.z, p[j].z, acc[i][j]);
                        acc[i][j] = fmaf(v.w, p[j].w, acc[i][j]);
                    }
                }
            }
        }
    }

    sSum[sN * 9 + w] = rowsum;
    __syncthreads();   // all GEMM reads of sP/sV done

    // ---- reduce 8 m-splits via butterfly shuffles (lanes differ in bits 2-4) ----
#pragma unroll
    for (int i = 0; i < 8; i++)
#pragma unroll
        for (int j = 0; j < 8; j++) {
            float v = acc[i][j];
            v += __shfl_xor_sync(0xffffffffu, v, 4);
            v += __shfl_xor_sync(0xffffffffu, v, 8);
            v += __shfl_xor_sync(0xffffffffu, v, 16);
            acc[i][j] = v;
        }
    float* sO = sP;       // 64 x 33, aliases sP
    if (msplit == 0) {
#pragma unroll
        for (int i = 0; i < 8; i++)
#pragma unroll
            for (int j = 0; j < 8; j++)
                sO[(c0 + i) * 33 + ngrp + 4 * j] = acc[i][j];
    }
    // stage wo as sWo[c][o] (aliases sV0 region)
    float* sWo = sm;      // 64 x 132
    for (int i = t; i < 8192; i += 256) {
        int o = i >> 6, c = i & 63;
        sWo[c * 132 + o] = wo[i];
    }
    __syncthreads();

    // ---- Phase 3: out[o][n] = gamma*inv[n]*sum_c wo[o][c]*o_raw[c][n] + x ----
    {
        float inv = 0.f;
#pragma unroll
        for (int r = 0; r < 8; r++) inv += sSum[lane * 9 + r];
        inv = 1.f / inv;

        float oa[16];
#pragma unroll
        for (int k = 0; k < 16; k++) oa[k] = 0.f;
#pragma unroll 4
        for (int c = 0; c < 64; c++) {
            float ov = sO[c * 33 + lane];
            const float4* w4 = (const float4*)&sWo[c * 132 + w * 16];
#pragma unroll
            for (int q4 = 0; q4 < 4; q4++) {
                float4 wv_ = w4[q4];
                oa[q4 * 4 + 0] = fmaf(wv_.x, ov, oa[q4 * 4 + 0]);
                oa[q4 * 4 + 1] = fmaf(wv_.y, ov, oa[q4 * 4 + 1]);
                oa[q4 * 4 + 2] = fmaf(wv_.z, ov, oa[q4 * 4 + 2]);
                oa[q4 * 4 + 3] = fmaf(wv_.w, ov, oa[q4 * 4 + 3]);
            }
        }
        const float gsc = gamma[0] * inv;
        const size_t base = (size_t)(b * 128) * N_PIX + n0 + lane;
#pragma unroll
        for (int k = 0; k < 16; k++) {
            size_t gi = base + (size_t)(w * 16 + k) * N_PIX;
            out[gi] = fmaf(gsc, oa[k], x[gi]);
        }
    }
}

// ---------------------------------------------------------------------------
extern "C" void kernel_launch(void* const* d_in, const int* in_sizes, int n_in,
                              void* d_out, int out_size)
{
    const float* x     = (const float*)d_in[0];
    const float* wq    = (const float*)d_in[1];
    const float* wk    = (const float*)d_in[2];
    const float* wv    = (const float*)d_in[3];
    const float* wo    = (const float*)d_in[4];
    const float* gamma = (const float*)d_in[5];
    float* out = (float*)d_out;

    const int smem1 = (12800 + 2176 + 8320) * 4;                  // 93184
    const int smem2 = (16896 + 4224 + 4224 + 512 + 288) * 4;      // 104576

    cudaFuncSetAttribute(proj_pool_kernel, cudaFuncAttributeMaxDynamicSharedMemorySize, smem1);
    cudaFuncSetAttribute(attn_kernel,      cudaFuncAttributeMaxDynamicSharedMemorySize, smem2);

    proj_pool_kernel<<<dim3(32, 16), 128, smem1>>>(x, wq, wk, wv);
    attn_kernel<<<dim3(128, 16), 256, smem2>>>(x, wo, gamma, out);
}

// round 8
// speedup vs baseline: 1.3688x; 1.3595x over previous
#include <cuda_runtime.h>
#include <cstdint>

#define N_PIX 4096
#define M_PIX 1024

// cp.async helpers (16B per op)
#define CPA(dst32, srcp) \
    asm volatile("cp.async.ca.shared.global [%0], [%1], 16;" :: "r"(dst32), "l"(srcp) : "memory")
#define CP_COMMIT() asm volatile("cp.async.commit_group;" ::: "memory")
#define CP_WAIT0()  asm volatile("cp.async.wait_group 0;" ::: "memory")

// tf32 round-to-nearest (result reinterpretable as f32 with low mantissa zeroed)
__device__ __forceinline__ float tf32r(float f) {
    uint32_t u;
    asm("cvt.rna.tf32.f32 %0, %1;" : "=r"(u) : "f"(f));
    return __uint_as_float(u);
}

// m16n8k8 tf32 MMA, D/C fp32
#define MMA_TF32(d, a0, a1, a2, a3, b0, b1) \
    asm volatile("mma.sync.aligned.m16n8k8.row.col.f32.tf32.tf32.f32 " \
        "{%0,%1,%2,%3}, {%4,%5,%6,%7}, {%8,%9}, {%0,%1,%2,%3};" \
        : "+f"(d[0]), "+f"(d[1]), "+f"(d[2]), "+f"(d[3]) \
        : "r"(a0), "r"(a1), "r"(a2), "r"(a3), "r"(b0), "r"(b1))

// Scratch (device globals — no allocation allowed)
__device__ __align__(16) float g_q[16 * 16 * N_PIX];   // [b][16][n]
__device__ __align__(16) float g_k[16 * 16 * M_PIX];   // [b][16][m]
__device__ __align__(16) float g_v[16 * 64 * M_PIX];   // [b][64][m]  (tf32-rounded)

// ---------------------------------------------------------------------------
// Kernel 1: q/k/v 1x1-conv + 2x2 maxpool. 128 threads = 128 pixels = 2 rows.
// Weights transposed in smem sWt[c][o]. V outputs tf32-rounded at final store
// (rounding is monotone, so it commutes with the max-pool).
// ---------------------------------------------------------------------------
__global__ __launch_bounds__(128) void proj_pool_kernel(
    const float* __restrict__ x,
    const float* __restrict__ wq,
    const float* __restrict__ wk,
    const float* __restrict__ wv)
{
    extern __shared__ float sm[];
    float* sWt = sm;                 // 128 * 100 = 12800
    float* kb  = sm + 12800;         // 128 * 17 = 2176
    float* vb  = kb + 2176;          // 128 * 65 = 8320

    const int t = threadIdx.x;
    for (int i = t; i < 12288; i += 128) {
        int o = i >> 7, c = i & 127;
        float wv_;
        if (o < 16)      wv_ = wq[i];
        else if (o < 32) wv_ = wk[i - 2048];
        else             wv_ = wv[i - 4096];
        sWt[c * 100 + o] = wv_;
    }
    __syncthreads();

    const int b = blockIdx.y;
    const int n = blockIdx.x * 128 + t;
    const float* xb = x + (size_t)b * 128 * N_PIX;

    float a[96];
#pragma unroll
    for (int o = 0; o < 96; o++) a[o] = 0.f;

#pragma unroll 4
    for (int c = 0; c < 128; c++) {
        float xv = xb[c * N_PIX + n];
        const float4* wrow = (const float4*)&sWt[c * 100];
#pragma unroll
        for (int jj = 0; jj < 24; jj++) {
            float4 w4 = wrow[jj];
            a[jj * 4 + 0] = fmaf(w4.x, xv, a[jj * 4 + 0]);
            a[jj * 4 + 1] = fmaf(w4.y, xv, a[jj * 4 + 1]);
            a[jj * 4 + 2] = fmaf(w4.z, xv, a[jj * 4 + 2]);
            a[jj * 4 + 3] = fmaf(w4.w, xv, a[jj * 4 + 3]);
        }
    }

#pragma unroll
    for (int o = 0; o < 16; o++) g_q[(b * 16 + o) * N_PIX + n] = a[o];
#pragma unroll
    for (int o = 0; o < 16; o++) kb[t * 17 + o] = a[16 + o];
#pragma unroll
    for (int o = 0; o < 64; o++) vb[t * 65 + o] = a[32 + o];
    __syncthreads();

    const int mbase = blockIdx.x * 32;
    for (int idx = t; idx < 2560; idx += 128) {
        int ch = idx >> 5, wp = idx & 31;
        int t00 = wp * 2, t01 = t00 + 1, t10 = t00 + 64, t11 = t00 + 65;
        if (ch < 16) {
            float r = fmaxf(fmaxf(kb[t00 * 17 + ch], kb[t01 * 17 + ch]),
                            fmaxf(kb[t10 * 17 + ch], kb[t11 * 17 + ch]));
            g_k[((b * 16 + ch) << 10) + mbase + wp] = r;
        } else {
            int c2 = ch - 16;
            float r = fmaxf(fmaxf(vb[t00 * 65 + c2], vb[t01 * 65 + c2]),
                            fmaxf(vb[t10 * 65 + c2], vb[t11 * 65 + c2]));
            g_v[((b * 64 + c2) << 10) + mbase + wp] = tf32r(r);
        }
    }
}

// ---------------------------------------------------------------------------
// Kernel 2: fused attention. S-phase in exact fp32 FFMA; O = V*P GEMM on the
// tensor pipe (mma.sync m16n8k8 tf32, V and P tf32-rounded). 256 threads,
// 2 CTAs/SM, cp.async double-buffered K/V staging.
// SMEM floats: sV[2]x8448, sK[2]x2112, sP 4224, sQ 512, sSum 288 = 104.6KB.
// ---------------------------------------------------------------------------
#define SV_OFF(buf)  ((buf) ? 8448u : 0u)
#define SK_OFF(buf)  (16896u + ((buf) ? 2112u : 0u))
#define SP_OFF       21120u
#define SQ_OFF       25344u
#define SSUM_OFF     25856u

__device__ __forceinline__ void stage_chunk(
    uint32_t sbase, int buf, int chk, int t,
    const float4* __restrict__ gk4, const float4* __restrict__ gv4)
{
    uint32_t kdst = sbase + SK_OFF(buf) * 4u;
    uint32_t vdst = sbase + SV_OFF(buf) * 4u;
#pragma unroll
    for (int q = 0; q < 2; q++) {
        int i = t + q * 256;
        int r = i >> 5, c = i & 31;
        CPA(kdst + (uint32_t)(r * 33 + c) * 16u, gk4 + r * 256 + chk * 32 + c);
    }
#pragma unroll
    for (int q = 0; q < 8; q++) {
        int i = t + q * 256;
        int r = i >> 5, c = i & 31;
        CPA(vdst + (uint32_t)(r * 33 + c) * 16u, gv4 + r * 256 + chk * 32 + c);
    }
}

__global__ __launch_bounds__(256, 2) void attn_kernel(
    const float* __restrict__ x,
    const float* __restrict__ wo,
    const float* __restrict__ gamma,
    float* __restrict__ out)
{
    extern __shared__ float sm[];
    float* sP   = sm + SP_OFF;        // 32*132
    float* sQ   = sm + SQ_OFF;        // 512
    float* sSum = sm + SSUM_OFF;      // 32*9

    const int t    = threadIdx.x;
    const int w    = t >> 5;          // warp 0..7
    const int lane = t & 31;
    const int b    = blockIdx.y;
    const int n0   = blockIdx.x * 32;

    const int sN  = lane;             // S-phase: n = lane, m-window = w*16
    const int g   = lane >> 2;        // MMA group id (0..7)
    const int tig = lane & 3;         // MMA thread-in-group
    const int cA0 = (w >> 1) * 16;    // MMA: warp's c-tile base
    const int nwb = (w & 1) * 16;     // MMA: warp's n-half base

    const uint32_t sbase = (uint32_t)__cvta_generic_to_shared(sm);
    const float4* gk4 = (const float4*)(g_k + b * 16 * M_PIX);
    const float4* gv4 = (const float4*)(g_v + b * 64 * M_PIX);

    // prologue: async-stage chunk 0, stage Q tile
    stage_chunk(sbase, 0, 0, t, gk4, gv4);
    CP_COMMIT();
    for (int i = t; i < 512; i += 256) {
        int dd = i >> 5, j = i & 31;
        sQ[i] = g_q[(b * 16 + dd) * N_PIX + n0 + j];
    }

    float d0[4] = {0.f, 0.f, 0.f, 0.f};   // n8-tile 0 of this warp's n-half
    float d1[4] = {0.f, 0.f, 0.f, 0.f};   // n8-tile 1
    float rowsum = 0.f;

    for (int chk = 0; chk < 8; chk++) {
        const int buf = chk & 1;
        const float* sK = sm + SK_OFF(buf);
        const float* sV = sm + SV_OFF(buf);

        CP_WAIT0();
        __syncthreads();   // chunk chk visible; everyone done with GEMM(chk-1)

        if (chk < 7) {
            stage_chunk(sbase, buf ^ 1, chk + 1, t, gk4, gv4);
            CP_COMMIT();
        }

        // ---- S-chunk (fp32 FFMA): n=sN, m in [w*16, w*16+16); exp; round ----
        {
            float4 sa[4];
#pragma unroll
            for (int k = 0; k < 4; k++) sa[k] = make_float4(0.f, 0.f, 0.f, 0.f);
#pragma unroll
            for (int dd = 0; dd < 16; dd++) {
                float qv = sQ[dd * 32 + sN];
#pragma unroll
                for (int k = 0; k < 4; k++) {
                    float4 kv = *(const float4*)&sK[dd * 132 + w * 16 + k * 4];
                    sa[k].x = fmaf(qv, kv.x, sa[k].x);
                    sa[k].y = fmaf(qv, kv.y, sa[k].y);
                    sa[k].z = fmaf(qv, kv.z, sa[k].z);
                    sa[k].w = fmaf(qv, kv.w, sa[k].w);
                }
            }
#pragma unroll
            for (int k = 0; k < 4; k++) {
                sa[k].x = tf32r(__expf(sa[k].x));
                sa[k].y = tf32r(__expf(sa[k].y));
                sa[k].z = tf32r(__expf(sa[k].z));
                sa[k].w = tf32r(__expf(sa[k].w));
                rowsum += sa[k].x + sa[k].y + sa[k].z + sa[k].w;
                *(float4*)&sP[sN * 132 + w * 16 + k * 4] = sa[k];
            }
        }
        __syncthreads();

        // ---- GEMM chunk on tensor pipe: O[c][n] += V[c][m] * P[n][m] ----
        {
            const float* aB = sV + (cA0 + g) * 132 + tig;
            const float* bB = sP + (nwb + g) * 132 + tig;
#pragma unroll
            for (int ks = 0; ks < 16; ks++) {
                const int mk = ks * 8;
                uint32_t a0 = __float_as_uint(aB[mk]);
                uint32_t a1 = __float_as_uint(aB[mk + 8 * 132]);
                uint32_t a2 = __float_as_uint(aB[mk + 4]);
                uint32_t a3 = __float_as_uint(aB[mk + 8 * 132 + 4]);
                uint32_t b0 = __float_as_uint(bB[mk]);
                uint32_t b1 = __float_as_uint(bB[mk + 4]);
                MMA_TF32(d0, a0, a1, a2, a3, b0, b1);
                uint32_t b2 = __float_as_uint(bB[mk + 8 * 132]);
                uint32_t b3 = __float_as_uint(bB[mk + 8 * 132 + 4]);
                MMA_TF32(d1, a0, a1, a2, a3, b2, b3);
            }
        }
    }

    sSum[sN * 9 + w] = rowsum;
    __syncthreads();   // all GEMM reads of sP/sV done before aliasing

    // ---- write O fragments to sO (stride 34, aliases sP region) ----
    float* sO = sP;       // 64 x 34 = 2176 <= 4224
    {
        int cn = nwb + 2 * tig;
        *(float2*)&sO[(cA0 + g)     * 34 + cn]     = make_float2(d0[0], d0[1]);
        *(float2*)&sO[(cA0 + g + 8) * 34 + cn]     = make_float2(d0[2], d0[3]);
        *(float2*)&sO[(cA0 + g)     * 34 + cn + 8] = make_float2(d1[0], d1[1]);
        *(float2*)&sO[(cA0 + g + 8) * 34 + cn + 8] = make_float2(d1[2], d1[3]);
    }
    // stage wo as sWo[c][o] (aliases sV0/sK region)
    float* sWo = sm;      // 64 x 132
    for (int i = t; i < 8192; i += 256) {
        int o = i >> 6, c = i & 63;
        sWo[c * 132 + o] = wo[i];
    }
    __syncthreads();

    // ---- Phase 3 (fp32): out[o][n] = gamma*inv[n]*sum_c wo[o][c]*O[c][n] + x ----
    {
        float inv = 0.f;
#pragma unroll
        for (int r = 0; r < 8; r++) inv += sSum[lane * 9 + r];
        inv = 1.f / inv;

        float oa[16];
#pragma unroll
        for (int k = 0; k < 16; k++) oa[k] = 0.f;
#pragma unroll 4
        for (int c = 0; c < 64; c++) {
            float ov = sO[c * 34 + lane];
            const float4* w4 = (const float4*)&sWo[c * 132 + w * 16];
#pragma unroll
            for (int q4 = 0; q4 < 4; q4++) {
                float4 wv_ = w4[q4];
                oa[q4 * 4 + 0] = fmaf(wv_.x, ov, oa[q4 * 4 + 0]);
                oa[q4 * 4 + 1] = fmaf(wv_.y, ov, oa[q4 * 4 + 1]);
                oa[q4 * 4 + 2] = fmaf(wv_.z, ov, oa[q4 * 4 + 2]);
                oa[q4 * 4 + 3] = fmaf(wv_.w, ov, oa[q4 * 4 + 3]);
            }
        }
        const float gsc = gamma[0] * inv;
        const size_t base = (size_t)(b * 128) * N_PIX + n0 + lane;
#pragma unroll
        for (int k = 0; k < 16; k++) {
            size_t gi = base + (size_t)(w * 16 + k) * N_PIX;
            out[gi] = fmaf(gsc, oa[k], x[gi]);
        }
    }
}

// ---------------------------------------------------------------------------
extern "C" void kernel_launch(void* const* d_in, const int* in_sizes, int n_in,
                              void* d_out, int out_size)
{
    const float* x     = (const float*)d_in[0];
    const float* wq    = (const float*)d_in[1];
    const float* wk    = (const float*)d_in[2];
    const float* wv    = (const float*)d_in[3];
    const float* wo    = (const float*)d_in[4];
    const float* gamma = (const float*)d_in[5];
    float* out = (float*)d_out;

    const int smem1 = (12800 + 2176 + 8320) * 4;                  // 93184
    const int smem2 = (16896 + 4224 + 4224 + 512 + 288) * 4;      // 104576

    cudaFuncSetAttribute(proj_pool_kernel, cudaFuncAttributeMaxDynamicSharedMemorySize, smem1);
    cudaFuncSetAttribute(attn_kernel,      cudaFuncAttributeMaxDynamicSharedMemorySize, smem2);

    proj_pool_kernel<<<dim3(32, 16), 128, smem1>>>(x, wq, wk, wv);
    attn_kernel<<<dim3(128, 16), 256, smem2>>>(x, wo, gamma, out);
}

// round 9
// speedup vs baseline: 1.6850x; 1.2310x over previous
#include <cuda_runtime.h>
#include <cuda_bf16.h>
#include <cstdint>

#define N_PIX 4096
#define M_PIX 1024

// cp.async helpers (16B per op)
#define CPA(dst32, srcp) \
    asm volatile("cp.async.ca.shared.global [%0], [%1], 16;" :: "r"(dst32), "l"(srcp) : "memory")
#define CP_COMMIT() asm volatile("cp.async.commit_group;" ::: "memory")
#define CP_WAIT0()  asm volatile("cp.async.wait_group 0;" ::: "memory")

// ldmatrix x4 (b16), per-lane row addressing
#define LDMX4(r0, r1, r2, r3, addr) \
    asm volatile("ldmatrix.sync.aligned.m8n8.x4.shared.b16 {%0,%1,%2,%3}, [%4];" \
        : "=r"(r0), "=r"(r1), "=r"(r2), "=r"(r3) : "r"(addr))

// m16n8k16 bf16 MMA, fp32 accumulate
#define MMA_BF16(d, a0, a1, a2, a3, b0, b1) \
    asm volatile("mma.sync.aligned.m16n8k16.row.col.f32.bf16.bf16.f32 " \
        "{%0,%1,%2,%3}, {%4,%5,%6,%7}, {%8,%9}, {%0,%1,%2,%3};" \
        : "+f"(d[0]), "+f"(d[1]), "+f"(d[2]), "+f"(d[3]) \
        : "r"(a0), "r"(a1), "r"(a2), "r"(a3), "r"(b0), "r"(b1))

// Scratch (device globals — no allocation allowed)
__device__ __align__(16) float         g_q[16 * 16 * N_PIX];   // [b][16][n] fp32
__device__ __align__(16) float         g_k[16 * 16 * M_PIX];   // [b][16][m] fp32
__device__ __align__(16) __nv_bfloat16 g_v[16 * 64 * M_PIX];   // [b][64][m] bf16

// ---------------------------------------------------------------------------
// Kernel 1: q/k/v 1x1-conv + 2x2 maxpool. 128 threads = 128 pixels = 2 rows.
// Weights transposed in smem sWt[c][o]; explicit 4-deep x prefetch.
// V stored bf16 (rounding is monotone -> commutes with maxpool).
// ---------------------------------------------------------------------------
__global__ __launch_bounds__(128) void proj_pool_kernel(
    const float* __restrict__ x,
    const float* __restrict__ wq,
    const float* __restrict__ wk,
    const float* __restrict__ wv)
{
    extern __shared__ float sm[];
    float* sWt = sm;                 // 128 * 100 = 12800
    float* kb  = sm + 12800;         // 128 * 17 = 2176
    float* vb  = kb + 2176;          // 128 * 65 = 8320

    const int t = threadIdx.x;
    for (int i = t; i < 12288; i += 128) {
        int o = i >> 7, c = i & 127;
        float wv_;
        if (o < 16)      wv_ = wq[i];
        else if (o < 32) wv_ = wk[i - 2048];
        else             wv_ = wv[i - 4096];
        sWt[c * 100 + o] = wv_;
    }
    __syncthreads();

    const int b = blockIdx.y;
    const int n = blockIdx.x * 128 + t;
    const float* xb = x + (size_t)b * 128 * N_PIX;

    float a[96];
#pragma unroll
    for (int o = 0; o < 96; o++) a[o] = 0.f;

    float xcur[4], xnxt[4];
#pragma unroll
    for (int cc = 0; cc < 4; cc++) xcur[cc] = xb[cc * N_PIX + n];

#pragma unroll 1
    for (int c8 = 0; c8 < 128; c8 += 4) {
        if (c8 + 4 < 128) {
#pragma unroll
            for (int cc = 0; cc < 4; cc++) xnxt[cc] = xb[(c8 + 4 + cc) * N_PIX + n];
        }
#pragma unroll
        for (int cc = 0; cc < 4; cc++) {
            float xv = xcur[cc];
            const float4* wrow = (const float4*)&sWt[(c8 + cc) * 100];
#pragma unroll
            for (int jj = 0; jj < 24; jj++) {
                float4 w4 = wrow[jj];
                a[jj * 4 + 0] = fmaf(w4.x, xv, a[jj * 4 + 0]);
                a[jj * 4 + 1] = fmaf(w4.y, xv, a[jj * 4 + 1]);
                a[jj * 4 + 2] = fmaf(w4.z, xv, a[jj * 4 + 2]);
                a[jj * 4 + 3] = fmaf(w4.w, xv, a[jj * 4 + 3]);
            }
        }
#pragma unroll
        for (int cc = 0; cc < 4; cc++) xcur[cc] = xnxt[cc];
    }

#pragma unroll
    for (int o = 0; o < 16; o++) g_q[(b * 16 + o) * N_PIX + n] = a[o];
#pragma unroll
    for (int o = 0; o < 16; o++) kb[t * 17 + o] = a[16 + o];
#pragma unroll
    for (int o = 0; o < 64; o++) vb[t * 65 + o] = a[32 + o];
    __syncthreads();

    const int mbase = blockIdx.x * 32;
    for (int idx = t; idx < 2560; idx += 128) {
        int ch = idx >> 5, wp = idx & 31;
        int t00 = wp * 2, t01 = t00 + 1, t10 = t00 + 64, t11 = t00 + 65;
        if (ch < 16) {
            float r = fmaxf(fmaxf(kb[t00 * 17 + ch], kb[t01 * 17 + ch]),
                            fmaxf(kb[t10 * 17 + ch], kb[t11 * 17 + ch]));
            g_k[((b * 16 + ch) << 10) + mbase + wp] = r;
        } else {
            int c2 = ch - 16;
            float r = fmaxf(fmaxf(vb[t00 * 65 + c2], vb[t01 * 65 + c2]),
                            fmaxf(vb[t10 * 65 + c2], vb[t11 * 65 + c2]));
            g_v[((b * 64 + c2) << 10) + mbase + wp] = __float2bfloat16_rn(r);
        }
    }
}

// ---------------------------------------------------------------------------
// Kernel 2: fused attention. S-phase exact fp32 FFMA; O = V*P on tensor pipe
// (mma m16n8k16 bf16, operands via ldmatrix.x4). 256 threads, 2 CTAs/SM,
// cp.async double-buffered K(fp32)/V(bf16) staging.
// SMEM floats: sV[2] 2x4352 (bf16 64x136), sK[2] 2x2112 (fp32 16x132),
//              sP 2176 (bf16 32x136), sQ 512, sSum 288 = 63.6KB.
// ---------------------------------------------------------------------------
#define SV_OFF(buf)  ((buf) ? 4352u : 0u)         // floats
#define SK_OFF(buf)  (8704u + ((buf) ? 2112u : 0u))
#define SP_OFF       12928u
#define SQ_OFF       15104u
#define SSUM_OFF     15616u

__device__ __forceinline__ void stage_chunk(
    uint32_t sbase, int buf, int chk, int t,
    const float4* __restrict__ gk4, const __nv_bfloat16* __restrict__ gvb)
{
    uint32_t kdst = sbase + SK_OFF(buf) * 4u;
    uint32_t vdst = sbase + SV_OFF(buf) * 4u;
#pragma unroll
    for (int q = 0; q < 2; q++) {
        int i = t + q * 256;
        int r = i >> 5, c = i & 31;
        CPA(kdst + (uint32_t)r * 528u + (uint32_t)c * 16u, gk4 + r * 256 + chk * 32 + c);
    }
#pragma unroll
    for (int q = 0; q < 4; q++) {
        int i = t + q * 256;                 // 0..1023
        int r = i >> 4, c8 = i & 15;         // row 0..63, 16B-slot 0..15
        CPA(vdst + (uint32_t)r * 272u + (uint32_t)c8 * 16u,
            gvb + ((size_t)r << 10) + chk * 128 + c8 * 8);
    }
}

__global__ __launch_bounds__(256, 2) void attn_kernel(
    const float* __restrict__ x,
    const float* __restrict__ wo,
    const float* __restrict__ gamma,
    float* __restrict__ out)
{
    extern __shared__ float sm[];
    float* sQ   = sm + SQ_OFF;        // 512
    float* sSum = sm + SSUM_OFF;      // 32*9
    __nv_bfloat16* sP16 = (__nv_bfloat16*)(sm + SP_OFF);  // [32][136]

    const int t    = threadIdx.x;
    const int w    = t >> 5;          // warp 0..7
    const int lane = t & 31;
    const int b    = blockIdx.y;
    const int n0   = blockIdx.x * 32;

    const int sN  = lane;             // S-phase: n = lane, m-window = w*16
    const int g   = lane >> 2;        // MMA group id
    const int tig = lane & 3;
    const int cA0 = (w >> 1) * 16;    // warp's c-tile base
    const int nwb = (w & 1) * 16;     // warp's n-half base

    const uint32_t sbase = (uint32_t)__cvta_generic_to_shared(sm);
    const float4* gk4 = (const float4*)(g_k + b * 16 * M_PIX);
    const __nv_bfloat16* gvb = g_v + (size_t)b * 64 * M_PIX;

    // ldmatrix per-lane addresses (bytes)
    const int matI = lane >> 3, ii = lane & 7;
    const uint32_t aRowOff = (uint32_t)(cA0 + ii + 8 * (matI & 1)) * 272u
                           + (uint32_t)(matI >> 1) * 16u;           // within V buf
    const uint32_t bAddr   = sbase + SP_OFF * 4u
                           + (uint32_t)(nwb + ii + 8 * (matI >> 1)) * 272u
                           + (uint32_t)(matI & 1) * 16u;

    // prologue: async-stage chunk 0, stage Q tile
    stage_chunk(sbase, 0, 0, t, gk4, gvb);
    CP_COMMIT();
    for (int i = t; i < 512; i += 256) {
        int dd = i >> 5, j = i & 31;
        sQ[i] = g_q[(b * 16 + dd) * N_PIX + n0 + j];
    }

    float d0[4] = {0.f, 0.f, 0.f, 0.f};
    float d1[4] = {0.f, 0.f, 0.f, 0.f};
    float rowsum = 0.f;

    for (int chk = 0; chk < 8; chk++) {
        const int buf = chk & 1;
        const float* sK = sm + SK_OFF(buf);

        CP_WAIT0();
        __syncthreads();   // chunk chk visible; everyone done with GEMM(chk-1)

        if (chk < 7) {
            stage_chunk(sbase, buf ^ 1, chk + 1, t, gk4, gvb);
            CP_COMMIT();
        }

        // ---- S-chunk (fp32): n=sN, m in [w*16, w*16+16); exp; bf16 round ----
        {
            float4 sa[4];
#pragma unroll
            for (int k = 0; k < 4; k++) sa[k] = make_float4(0.f, 0.f, 0.f, 0.f);
#pragma unroll
            for (int dd = 0; dd < 16; dd++) {
                float qv = sQ[dd * 32 + sN];
#pragma unroll
                for (int k = 0; k < 4; k++) {
                    float4 kv = *(const float4*)&sK[dd * 132 + w * 16 + k * 4];
                    sa[k].x = fmaf(qv, kv.x, sa[k].x);
                    sa[k].y = fmaf(qv, kv.y, sa[k].y);
                    sa[k].z = fmaf(qv, kv.z, sa[k].z);
                    sa[k].w = fmaf(qv, kv.w, sa[k].w);
                }
            }
#pragma unroll
            for (int k = 0; k < 4; k++) {
                __nv_bfloat162 h0 = __float22bfloat162_rn(
                    make_float2(__expf(sa[k].x), __expf(sa[k].y)));
                __nv_bfloat162 h1 = __float22bfloat162_rn(
                    make_float2(__expf(sa[k].z), __expf(sa[k].w)));
                rowsum += __low2float(h0) + __high2float(h0)
                        + __low2float(h1) + __high2float(h1);
                uint2 pk;
                pk.x = *reinterpret_cast<uint32_t*>(&h0);
                pk.y = *reinterpret_cast<uint32_t*>(&h1);
                *(uint2*)(sP16 + sN * 136 + w * 16 + k * 4) = pk;
            }
        }
        __syncthreads();

        // ---- GEMM chunk (tensor pipe): O[c][n] += V[c][m] * P[n][m] ----
        {
            const uint32_t aBase = sbase + SV_OFF(buf) * 4u + aRowOff;
#pragma unroll
            for (int ks = 0; ks < 8; ks++) {
                uint32_t a0, a1, a2, a3, b0, b1, b2, b3;
                LDMX4(a0, a1, a2, a3, aBase + (uint32_t)ks * 32u);
                LDMX4(b0, b1, b2, b3, bAddr + (uint32_t)ks * 32u);
                MMA_BF16(d0, a0, a1, a2, a3, b0, b1);
                MMA_BF16(d1, a0, a1, a2, a3, b2, b3);
            }
        }
    }

    sSum[sN * 9 + w] = rowsum;
    __syncthreads();   // all GEMM reads of sP/sV done before aliasing

    // ---- write O fragments to sO (fp32, stride 34; aliases sP region) ----
    float* sO = sm + SP_OFF;     // 64 x 34 = 2176 floats (exact fit)
    {
        int cn = nwb + 2 * tig;
        *(float2*)&sO[(cA0 + g)     * 34 + cn]     = make_float2(d0[0], d0[1]);
        *(float2*)&sO[(cA0 + g + 8) * 34 + cn]     = make_float2(d0[2], d0[3]);
        *(float2*)&sO[(cA0 + g)     * 34 + cn + 8] = make_float2(d1[0], d1[1]);
        *(float2*)&sO[(cA0 + g + 8) * 34 + cn + 8] = make_float2(d1[2], d1[3]);
    }
    // stage wo as sWo[c][o] (aliases sV region, 8448 <= 8704 floats)
    float* sWo = sm;             // 64 x 132
    for (int i = t; i < 8192; i += 256) {
        int o = i >> 6, c = i & 63;
        sWo[c * 132 + o] = wo[i];
    }
    __syncthreads();

    // ---- Phase 3 (fp32): out[o][n] = gamma*inv[n]*sum_c wo[o][c]*O[c][n]+x ----
    {
        float inv = 0.f;
#pragma unroll
        for (int r = 0; r < 8; r++) inv += sSum[lane * 9 + r];
        inv = 1.f / inv;

        float oa[16];
#pragma unroll
        for (int k = 0; k < 16; k++) oa[k] = 0.f;
#pragma unroll 4
        for (int c = 0; c < 64; c++) {
            float ov = sO[c * 34 + lane];
            const float4* w4 = (const float4*)&sWo[c * 132 + w * 16];
#pragma unroll
            for (int q4 = 0; q4 < 4; q4++) {
                float4 wv_ = w4[q4];
                oa[q4 * 4 + 0] = fmaf(wv_.x, ov, oa[q4 * 4 + 0]);
                oa[q4 * 4 + 1] = fmaf(wv_.y, ov, oa[q4 * 4 + 1]);
                oa[q4 * 4 + 2] = fmaf(wv_.z, ov, oa[q4 * 4 + 2]);
                oa[q4 * 4 + 3] = fmaf(wv_.w, ov, oa[q4 * 4 + 3]);
            }
        }
        const float gsc = gamma[0] * inv;
        const size_t base = (size_t)(b * 128) * N_PIX + n0 + lane;
#pragma unroll
        for (int k = 0; k < 16; k++) {
            size_t gi = base + (size_t)(w * 16 + k) * N_PIX;
            out[gi] = fmaf(gsc, oa[k], x[gi]);
        }
    }
}

// ---------------------------------------------------------------------------
extern "C" void kernel_launch(void* const* d_in, const int* in_sizes, int n_in,
                              void* d_out, int out_size)
{
    const float* x     = (const float*)d_in[0];
    const float* wq    = (const float*)d_in[1];
    const float* wk    = (const float*)d_in[2];
    const float* wv    = (const float*)d_in[3];
    const float* wo    = (const float*)d_in[4];
    const float* gamma = (const float*)d_in[5];
    float* out = (float*)d_out;

    const int smem1 = (12800 + 2176 + 8320) * 4;   // 93184
    const int smem2 = 15904 * 4;                   // 63616

    cudaFuncSetAttribute(proj_pool_kernel, cudaFuncAttributeMaxDynamicSharedMemorySize, smem1);
    cudaFuncSetAttribute(attn_kernel,      cudaFuncAttributeMaxDynamicSharedMemorySize, smem2);

    proj_pool_kernel<<<dim3(32, 16), 128, smem1>>>(x, wq, wk, wv);
    attn_kernel<<<dim3(128, 16), 256, smem2>>>(x, wo, gamma, out);
}

// round 10
// speedup vs baseline: 2.2677x; 1.3458x over previous
#include <cuda_runtime.h>
#include <cuda_bf16.h>
#include <cstdint>

#define N_PIX 4096
#define M_PIX 1024

// cp.async helpers (16B per op)
#define CPA(dst32, srcp) \
    asm volatile("cp.async.ca.shared.global [%0], [%1], 16;" :: "r"(dst32), "l"(srcp) : "memory")
#define CP_COMMIT() asm volatile("cp.async.commit_group;" ::: "memory")
#define CP_WAIT0()  asm volatile("cp.async.wait_group 0;" ::: "memory")

// ldmatrix x4 (b16), per-lane row addressing
#define LDMX4(r0, r1, r2, r3, addr) \
    asm volatile("ldmatrix.sync.aligned.m8n8.x4.shared.b16 {%0,%1,%2,%3}, [%4];" \
        : "=r"(r0), "=r"(r1), "=r"(r2), "=r"(r3) : "r"(addr))

// m16n8k16 bf16 MMA, fp32 accumulate
#define MMA_BF16(d, a0, a1, a2, a3, b0, b1) \
    asm volatile("mma.sync.aligned.m16n8k16.row.col.f32.bf16.bf16.f32 " \
        "{%0,%1,%2,%3}, {%4,%5,%6,%7}, {%8,%9}, {%0,%1,%2,%3};" \
        : "+f"(d[0]), "+f"(d[1]), "+f"(d[2]), "+f"(d[3]) \
        : "r"(a0), "r"(a1), "r"(a2), "r"(a3), "r"(b0), "r"(b1))

// m16n8k8 tf32 MMA, fp32 accumulate
#define MMA_TF32(d, a0, a1, a2, a3, b0, b1) \
    asm volatile("mma.sync.aligned.m16n8k8.row.col.f32.tf32.tf32.f32 " \
        "{%0,%1,%2,%3}, {%4,%5,%6,%7}, {%8,%9}, {%0,%1,%2,%3};" \
        : "+f"(d[0]), "+f"(d[1]), "+f"(d[2]), "+f"(d[3]) \
        : "r"(a0), "r"(a1), "r"(a2), "r"(a3), "r"(b0), "r"(b1))

// tf32 round-to-nearest
__device__ __forceinline__ float tf32r(float f) {
    uint32_t u;
    asm("cvt.rna.tf32.f32 %0, %1;" : "=r"(u) : "f"(f));
    return __uint_as_float(u);
}

// Scratch (device globals — no allocation allowed)
__device__ __align__(16) float         g_q[16 * 16 * N_PIX];   // [b][16][n] tf32-in-f32
__device__ __align__(16) float         g_k[16 * 16 * M_PIX];   // [b][16][m] tf32-in-f32
__device__ __align__(16) __nv_bfloat16 g_v[16 * 64 * M_PIX];   // [b][64][m] bf16

// ---------------------------------------------------------------------------
// Kernel 1: q/k/v 1x1-conv + 2x2 maxpool. 128 threads = 128 pixels = 2 rows.
// Weights transposed in smem sWt[c][o]; 4-deep x prefetch. Q/K stored
// tf32-rounded, V bf16 (rounding monotone -> commutes with maxpool).
// ---------------------------------------------------------------------------
__global__ __launch_bounds__(128) void proj_pool_kernel(
    const float* __restrict__ x,
    const float* __restrict__ wq,
    const float* __restrict__ wk,
    const float* __restrict__ wv)
{
    extern __shared__ float sm[];
    float* sWt = sm;                 // 128 * 100 = 12800
    float* kb  = sm + 12800;         // 128 * 17 = 2176
    float* vb  = kb + 2176;          // 128 * 65 = 8320

    const int t = threadIdx.x;
    for (int i = t; i < 12288; i += 128) {
        int o = i >> 7, c = i & 127;
        float wv_;
        if (o < 16)      wv_ = wq[i];
        else if (o < 32) wv_ = wk[i - 2048];
        else             wv_ = wv[i - 4096];
        sWt[c * 100 + o] = wv_;
    }
    __syncthreads();

    const int b = blockIdx.y;
    const int n = blockIdx.x * 128 + t;
    const float* xb = x + (size_t)b * 128 * N_PIX;

    float a[96];
#pragma unroll
    for (int o = 0; o < 96; o++) a[o] = 0.f;

    float xcur[4], xnxt[4];
#pragma unroll
    for (int cc = 0; cc < 4; cc++) xcur[cc] = xb[cc * N_PIX + n];

#pragma unroll 1
    for (int c8 = 0; c8 < 128; c8 += 4) {
        if (c8 + 4 < 128) {
#pragma unroll
            for (int cc = 0; cc < 4; cc++) xnxt[cc] = xb[(c8 + 4 + cc) * N_PIX + n];
        }
#pragma unroll
        for (int cc = 0; cc < 4; cc++) {
            float xv = xcur[cc];
            const float4* wrow = (const float4*)&sWt[(c8 + cc) * 100];
#pragma unroll
            for (int jj = 0; jj < 24; jj++) {
                float4 w4 = wrow[jj];
                a[jj * 4 + 0] = fmaf(w4.x, xv, a[jj * 4 + 0]);
                a[jj * 4 + 1] = fmaf(w4.y, xv, a[jj * 4 + 1]);
                a[jj * 4 + 2] = fmaf(w4.z, xv, a[jj * 4 + 2]);
                a[jj * 4 + 3] = fmaf(w4.w, xv, a[jj * 4 + 3]);
            }
        }
#pragma unroll
        for (int cc = 0; cc < 4; cc++) xcur[cc] = xnxt[cc];
    }

#pragma unroll
    for (int o = 0; o < 16; o++) g_q[(b * 16 + o) * N_PIX + n] = tf32r(a[o]);
#pragma unroll
    for (int o = 0; o < 16; o++) kb[t * 17 + o] = a[16 + o];
#pragma unroll
    for (int o = 0; o < 64; o++) vb[t * 65 + o] = a[32 + o];
    __syncthreads();

    const int mbase = blockIdx.x * 32;
    for (int idx = t; idx < 2560; idx += 128) {
        int ch = idx >> 5, wp = idx & 31;
        int t00 = wp * 2, t01 = t00 + 1, t10 = t00 + 64, t11 = t00 + 65;
        if (ch < 16) {
            float r = fmaxf(fmaxf(kb[t00 * 17 + ch], kb[t01 * 17 + ch]),
                            fmaxf(kb[t10 * 17 + ch], kb[t11 * 17 + ch]));
            g_k[((b * 16 + ch) << 10) + mbase + wp] = tf32r(r);
        } else {
            int c2 = ch - 16;
            float r = fmaxf(fmaxf(vb[t00 * 65 + c2], vb[t01 * 65 + c2]),
                            fmaxf(vb[t10 * 65 + c2], vb[t11 * 65 + c2]));
            g_v[((b * 64 + c2) << 10) + mbase + wp] = __float2bfloat16_rn(r);
        }
    }
}

// ---------------------------------------------------------------------------
// Kernel 2: fully-tensorized fused attention. 256 threads, 2 CTAs/SM.
// S = Q^T K on tf32 MMA; P bf16; O = V*P on bf16 MMA (ldmatrix); epilogue
// wo*O on tf32 MMA. cp.async double-buffered K/V staging.
// SMEM floats: sV[2] 2x4352 (bf16 64x136), sK[2] 2x2176 (f32 16x136),
//              sP 2176 (bf16 32x136), sQ 528, sSum 160, sInv 32 = 62.3KB.
// ---------------------------------------------------------------------------
#define SV_OFF(buf)  ((buf) ? 4352u : 0u)
#define SK_OFF(buf)  (8704u + ((buf) ? 2176u : 0u))
#define SP_OFF       13056u
#define SQ_OFF       15232u
#define SSUM_OFF     15760u
#define SINV_OFF     15920u
#define SMEM2_FLOATS 15952

__device__ __forceinline__ void stage_chunk(
    uint32_t sbase, int buf, int chk, int t,
    const float4* __restrict__ gk4, const __nv_bfloat16* __restrict__ gvb)
{
    uint32_t kdst = sbase + SK_OFF(buf) * 4u;
    uint32_t vdst = sbase + SV_OFF(buf) * 4u;
#pragma unroll
    for (int q = 0; q < 2; q++) {
        int i = t + q * 256;
        int r = i >> 5, c = i & 31;
        CPA(kdst + (uint32_t)r * 544u + (uint32_t)c * 16u, gk4 + r * 256 + chk * 32 + c);
    }
#pragma unroll
    for (int q = 0; q < 4; q++) {
        int i = t + q * 256;                 // 0..1023
        int r = i >> 4, c8 = i & 15;         // row 0..63, 16B-slot 0..15
        CPA(vdst + (uint32_t)r * 272u + (uint32_t)c8 * 16u,
            gvb + ((size_t)r << 10) + chk * 128 + c8 * 8);
    }
}

__global__ __launch_bounds__(256, 2) void attn_kernel(
    const float* __restrict__ x,
    const float* __restrict__ wo,
    const float* __restrict__ gamma,
    float* __restrict__ out)
{
    extern __shared__ float sm[];
    float* sQ   = sm + SQ_OFF;        // 16 x 33
    float* sSum = sm + SSUM_OFF;      // 32 x 5
    float* sInv = sm + SINV_OFF;      // 32
    __nv_bfloat16* sP16 = (__nv_bfloat16*)(sm + SP_OFF);  // [32][136]

    const int t    = threadIdx.x;
    const int w    = t >> 5;          // warp 0..7
    const int lane = t & 31;
    const int b    = blockIdx.y;
    const int n0   = blockIdx.x * 32;

    const int g   = lane >> 2;        // MMA group id (0..7)
    const int tig = lane & 3;         // thread-in-group
    // S-phase warp tile: n-half + m-quarter
    const int nh  = (w & 1) * 16;
    const int mq  = (w >> 1) * 32;
    // O-GEMM warp tile (unchanged from R9)
    const int cA0 = (w >> 1) * 16;
    const int nwb = (w & 1) * 16;
    // epilogue warp tile
    const int o0  = w * 16;

    const uint32_t sbase = (uint32_t)__cvta_generic_to_shared(sm);
    const float4* gk4 = (const float4*)(g_k + b * 16 * M_PIX);
    const __nv_bfloat16* gvb = g_v + (size_t)b * 64 * M_PIX;

    // ldmatrix per-lane addresses for O-GEMM (bytes), as in R9
    const int matI = lane >> 3, ii = lane & 7;
    const uint32_t aRowOff = (uint32_t)(cA0 + ii + 8 * (matI & 1)) * 272u
                           + (uint32_t)(matI >> 1) * 16u;
    const uint32_t bAddr   = sbase + SP_OFF * 4u
                           + (uint32_t)(nwb + ii + 8 * (matI >> 1)) * 272u
                           + (uint32_t)(matI & 1) * 16u;

    // prologue: async-stage chunk 0, stage Q tile [16][33]
    stage_chunk(sbase, 0, 0, t, gk4, gvb);
    CP_COMMIT();
    for (int i = t; i < 512; i += 256) {
        int dd = i >> 5, j = i & 31;
        sQ[dd * 33 + j] = g_q[(b * 16 + dd) * N_PIX + n0 + j];
    }
    __syncthreads();

    // hoist Q A-fragments (loop-invariant over chunks): qa[ks][0..3]
    uint32_t qa[2][4];
#pragma unroll
    for (int ks = 0; ks < 2; ks++) {
        qa[ks][0] = __float_as_uint(sQ[(ks * 8 + tig)     * 33 + nh + g]);
        qa[ks][1] = __float_as_uint(sQ[(ks * 8 + tig)     * 33 + nh + g + 8]);
        qa[ks][2] = __float_as_uint(sQ[(ks * 8 + tig + 4) * 33 + nh + g]);
        qa[ks][3] = __float_as_uint(sQ[(ks * 8 + tig + 4) * 33 + nh + g + 8]);
    }

    float d0[4] = {0.f, 0.f, 0.f, 0.f};   // O-GEMM acc, n8-tile 0
    float d1[4] = {0.f, 0.f, 0.f, 0.f};   // O-GEMM acc, n8-tile 1
    float rs0 = 0.f, rs1 = 0.f;           // rowsums for rows nh+g, nh+g+8

    for (int chk = 0; chk < 8; chk++) {
        const int buf = chk & 1;
        const float* sK = sm + SK_OFF(buf);

        CP_WAIT0();
        __syncthreads();   // chunk chk visible; everyone done with GEMM(chk-1)

        if (chk < 7) {
            stage_chunk(sbase, buf ^ 1, chk + 1, t, gk4, gvb);
            CP_COMMIT();
        }

        // ---- S-chunk on tf32 MMA: warp tile 16n x 32m ----
        float sd[4][4];
#pragma unroll
        for (int j = 0; j < 4; j++)
#pragma unroll
            for (int k = 0; k < 4; k++) sd[j][k] = 0.f;

#pragma unroll
        for (int ks = 0; ks < 2; ks++) {
#pragma unroll
            for (int j = 0; j < 4; j++) {
                uint32_t b0 = __float_as_uint(sK[(ks * 8 + tig)     * 136 + mq + 8 * j + g]);
                uint32_t b1 = __float_as_uint(sK[(ks * 8 + tig + 4) * 136 + mq + 8 * j + g]);
                MMA_TF32(sd[j], qa[ks][0], qa[ks][1], qa[ks][2], qa[ks][3], b0, b1);
            }
        }

        // ---- exp, bf16 round, rowsum, store P fragments ----
#pragma unroll
        for (int j = 0; j < 4; j++) {
            __nv_bfloat162 h0 = __float22bfloat162_rn(
                make_float2(__expf(sd[j][0]), __expf(sd[j][1])));
            __nv_bfloat162 h1 = __float22bfloat162_rn(
                make_float2(__expf(sd[j][2]), __expf(sd[j][3])));
            rs0 += __low2float(h0) + __high2float(h0);
            rs1 += __low2float(h1) + __high2float(h1);
            int mcol = mq + 8 * j + 2 * tig;
            *(uint32_t*)(sP16 + (nh + g)     * 136 + mcol) = *reinterpret_cast<uint32_t*>(&h0);
            *(uint32_t*)(sP16 + (nh + g + 8) * 136 + mcol) = *reinterpret_cast<uint32_t*>(&h1);
        }
        __syncthreads();

        // ---- O-GEMM chunk (bf16 tensor): O[c][n] += V[c][m] * P[n][m] ----
        {
            const uint32_t aBase = sbase + SV_OFF(buf) * 4u + aRowOff;
#pragma unroll
            for (int ks = 0; ks < 8; ks++) {
                uint32_t a0, a1, a2, a3, b0, b1, b2, b3;
                LDMX4(a0, a1, a2, a3, aBase + (uint32_t)ks * 32u);
                LDMX4(b0, b1, b2, b3, bAddr + (uint32_t)ks * 32u);
                MMA_BF16(d0, a0, a1, a2, a3, b0, b1);
                MMA_BF16(d1, a0, a1, a2, a3, b2, b3);
            }
        }
    }
    __syncthreads();   // all reads of sK/sV/sP done before aliasing

    // ---- write O fragments tf32-rounded to sO (stride 40; aliases sK) ----
    float* sO = sm + 8704;       // 64 x 40 = 2560 floats in sK region (4352)
    {
        int cn = nwb + 2 * tig;
        sO[(cA0 + g)     * 40 + cn]     = tf32r(d0[0]);
        sO[(cA0 + g)     * 40 + cn + 1] = tf32r(d0[1]);
        sO[(cA0 + g + 8) * 40 + cn]     = tf32r(d0[2]);
        sO[(cA0 + g + 8) * 40 + cn + 1] = tf32r(d0[3]);
        sO[(cA0 + g)     * 40 + cn + 8] = tf32r(d1[0]);
        sO[(cA0 + g)     * 40 + cn + 9] = tf32r(d1[1]);
        sO[(cA0 + g + 8) * 40 + cn + 8] = tf32r(d1[2]);
        sO[(cA0 + g + 8) * 40 + cn + 9] = tf32r(d1[3]);
    }
    // ---- rowsum reduce over tig (m within quarter), store per-quarter ----
    rs0 += __shfl_xor_sync(0xffffffffu, rs0, 1);
    rs0 += __shfl_xor_sync(0xffffffffu, rs0, 2);
    rs1 += __shfl_xor_sync(0xffffffffu, rs1, 1);
    rs1 += __shfl_xor_sync(0xffffffffu, rs1, 2);
    if (tig == 0) {
        sSum[(nh + g)     * 5 + (w >> 1)] = rs0;
        sSum[(nh + g + 8) * 5 + (w >> 1)] = rs1;
    }
    // ---- stage wo tf32-rounded as sWo[c][o] stride 136 (aliases sV) ----
    float* sWo = sm;             // 64 x 136 = 8704 floats (exact sV fit)
    for (int i = t; i < 8192; i += 256) {
        int o = i >> 6, c = i & 63;
        sWo[c * 136 + o] = tf32r(wo[i]);
    }
    __syncthreads();

    if (t < 32) {
        float s = sSum[t * 5] + sSum[t * 5 + 1] + sSum[t * 5 + 2] + sSum[t * 5 + 3];
        sInv[t] = 1.f / s;
    }
    __syncthreads();

    // ---- epilogue on tf32 MMA: out[o][n] = gamma*inv[n]*(wo.O)[o][n] + x ----
    {
        float od[4][4];
#pragma unroll
        for (int j = 0; j < 4; j++)
#pragma unroll
            for (int k = 0; k < 4; k++) od[j][k] = 0.f;

#pragma unroll
        for (int ks = 0; ks < 8; ks++) {
            uint32_t a0 = __float_as_uint(sWo[(8 * ks + tig)     * 136 + o0 + g]);
            uint32_t a1 = __float_as_uint(sWo[(8 * ks + tig)     * 136 + o0 + g + 8]);
            uint32_t a2 = __float_as_uint(sWo[(8 * ks + tig + 4) * 136 + o0 + g]);
            uint32_t a3 = __float_as_uint(sWo[(8 * ks + tig + 4) * 136 + o0 + g + 8]);
#pragma unroll
            for (int j = 0; j < 4; j++) {
                uint32_t b0 = __float_as_uint(sO[(8 * ks + tig)     * 40 + 8 * j + g]);
                uint32_t b1 = __float_as_uint(sO[(8 * ks + tig + 4) * 40 + 8 * j + g]);
                MMA_TF32(od[j], a0, a1, a2, a3, b0, b1);
            }
        }

        const float gm = gamma[0];
#pragma unroll
        for (int j = 0; j < 4; j++) {
            int nn = 8 * j + 2 * tig;
            float s0 = gm * sInv[nn];
            float s1 = gm * sInv[nn + 1];
            size_t gi0 = ((size_t)(b * 128 + o0 + g)) * N_PIX + n0 + nn;
            size_t gi1 = ((size_t)(b * 128 + o0 + g + 8)) * N_PIX + n0 + nn;
            float2 x0 = *(const float2*)&x[gi0];
            float2 x1 = *(const float2*)&x[gi1];
            float2 r0, r1;
            r0.x = fmaf(s0, od[j][0], x0.x);
            r0.y = fmaf(s1, od[j][1], x0.y);
            r1.x = fmaf(s0, od[j][2], x1.x);
            r1.y = fmaf(s1, od[j][3], x1.y);
            *(float2*)&out[gi0] = r0;
            *(float2*)&out[gi1] = r1;
        }
    }
}

// ---------------------------------------------------------------------------
extern "C" void kernel_launch(void* const* d_in, const int* in_sizes, int n_in,
                              void* d_out, int out_size)
{
    const float* x     = (const float*)d_in[0];
    const float* wq    = (const float*)d_in[1];
    const float* wk    = (const float*)d_in[2];
    const float* wv    = (const float*)d_in[3];
    const float* wo    = (const float*)d_in[4];
    const float* gamma = (const float*)d_in[5];
    float* out = (float*)d_out;

    const int smem1 = (12800 + 2176 + 8320) * 4;   // 93184
    const int smem2 = SMEM2_FLOATS * 4;            // 63808

    cudaFuncSetAttribute(proj_pool_kernel, cudaFuncAttributeMaxDynamicSharedMemorySize, smem1);
    cudaFuncSetAttribute(attn_kernel,      cudaFuncAttributeMaxDynamicSharedMemorySize, smem2);

    proj_pool_kernel<<<dim3(32, 16), 128, smem1>>>(x, wq, wk, wv);
    attn_kernel<<<dim3(128, 16), 256, smem2>>>(x, wo, gamma, out);
}

// round 11
// speedup vs baseline: 3.1990x; 1.4107x over previous
#include <cuda_runtime.h>
#include <cuda_bf16.h>
#include <cstdint>

#define N_PIX 4096
#define M_PIX 1024

// cp.async helpers (16B per op)
#define CPA(dst32, srcp) \
    asm volatile("cp.async.ca.shared.global [%0], [%1], 16;" :: "r"(dst32), "l"(srcp) : "memory")
#define CP_COMMIT() asm volatile("cp.async.commit_group;" ::: "memory")
#define CP_WAIT0()  asm volatile("cp.async.wait_group 0;" ::: "memory")

// ldmatrix x4 (b16), per-lane row addressing
#define LDMX4(r0, r1, r2, r3, addr) \
    asm volatile("ldmatrix.sync.aligned.m8n8.x4.shared.b16 {%0,%1,%2,%3}, [%4];" \
        : "=r"(r0), "=r"(r1), "=r"(r2), "=r"(r3) : "r"(addr))

// m16n8k16 bf16 MMA, fp32 accumulate
#define MMA_BF16(d, a0, a1, a2, a3, b0, b1) \
    asm volatile("mma.sync.aligned.m16n8k16.row.col.f32.bf16.bf16.f32 " \
        "{%0,%1,%2,%3}, {%4,%5,%6,%7}, {%8,%9}, {%0,%1,%2,%3};" \
        : "+f"(d[0]), "+f"(d[1]), "+f"(d[2]), "+f"(d[3]) \
        : "r"(a0), "r"(a1), "r"(a2), "r"(a3), "r"(b0), "r"(b1))

// m16n8k8 tf32 MMA, fp32 accumulate
#define MMA_TF32(d, a0, a1, a2, a3, b0, b1) \
    asm volatile("mma.sync.aligned.m16n8k8.row.col.f32.tf32.tf32.f32 " \
        "{%0,%1,%2,%3}, {%4,%5,%6,%7}, {%8,%9}, {%0,%1,%2,%3};" \
        : "+f"(d[0]), "+f"(d[1]), "+f"(d[2]), "+f"(d[3]) \
        : "r"(a0), "r"(a1), "r"(a2), "r"(a3), "r"(b0), "r"(b1))

// tf32 round-to-nearest
__device__ __forceinline__ float tf32r(float f) {
    uint32_t u;
    asm("cvt.rna.tf32.f32 %0, %1;" : "=r"(u) : "f"(f));
    return __uint_as_float(u);
}
__device__ __forceinline__ uint32_t tf32u(float f) {
    uint32_t u;
    asm("cvt.rna.tf32.f32 %0, %1;" : "=r"(u) : "f"(f));
    return u;
}

// Scratch (device globals — no allocation allowed)
__device__ __align__(16) float         g_q[16 * 16 * N_PIX];   // [b][16][n] tf32-in-f32
__device__ __align__(16) float         g_k[16 * 16 * M_PIX];   // [b][16][m] tf32-in-f32
__device__ __align__(16) __nv_bfloat16 g_v[16 * 64 * M_PIX];   // [b][64][m] bf16

// ---------------------------------------------------------------------------
// Kernel 1 (tensorized): out[96][128px] = W[96][128] * x[128][128px] on tf32
// MMA, then 2x2 maxpool for k/v. CTA = 128 px = 2 image rows = 1 pooled row.
// 256 threads, 8 warps x 16-px slices. x streamed in 4 k-chunks of 32
// channels via double-buffered cp.async; W staged tf32-rounded (stride 132,
// conflict-free A-frags); x B-frags tf32-rounded at load (stride 136).
// ---------------------------------------------------------------------------
#define K1_SW   0
#define K1_XS   12672              // floats; 2 buffers of 32x136 = 4352
#define K1_SMEM (12672 + 2 * 4352) // 21376 floats = 85504 B

__global__ __launch_bounds__(256, 2) void proj_pool_kernel(
    const float* __restrict__ x,
    const float* __restrict__ wq,
    const float* __restrict__ wk,
    const float* __restrict__ wv)
{
    extern __shared__ float sm[];
    float* sW = sm;                  // 96 x 132
    const int t    = threadIdx.x;
    const int lane = t & 31;
    const int w    = t >> 5;
    const int g    = lane >> 2;
    const int tig  = lane & 3;
    const int b    = blockIdx.y;
    const int px0  = blockIdx.x * 128;

    const float* xb = x + (size_t)b * 128 * N_PIX;
    const uint32_t sbase = (uint32_t)__cvta_generic_to_shared(sm);

    // ---- stage x chunk 0 (channels 0..31) ----
#pragma unroll
    for (int q = 0; q < 4; q++) {
        int i = t + q * 256;               // 0..1023
        int r = i >> 5, c16 = i & 31;
        CPA(sbase + (uint32_t)(K1_XS + r * 136 + c16 * 4) * 4u,
            xb + (size_t)r * N_PIX + px0 + c16 * 4);
    }
    CP_COMMIT();

    // ---- stage weights tf32-rounded: sW[o][c], stride 132 ----
    for (int i = t; i < 12288; i += 256) {
        int o = i >> 7, c = i & 127;
        float wv_;
        if (o < 16)      wv_ = wq[i];
        else if (o < 32) wv_ = wk[i - 2048];
        else             wv_ = wv[i - 4096];
        sW[o * 132 + c] = tf32r(wv_);
    }

    float dd[6][8];
#pragma unroll
    for (int mt = 0; mt < 6; mt++)
#pragma unroll
        for (int j = 0; j < 8; j++) dd[mt][j] = 0.f;

    const int nA = w * 16;                 // warp's 16-px slice

#pragma unroll 1
    for (int kc = 0; kc < 4; kc++) {
        const int buf = kc & 1;
        CP_WAIT0();
        __syncthreads();                   // chunk kc (and weights on kc=0) visible

        if (kc < 3) {
#pragma unroll
            for (int q = 0; q < 4; q++) {
                int i = t + q * 256;
                int r = i >> 5, c16 = i & 31;
                CPA(sbase + (uint32_t)(K1_XS + (buf ^ 1) * 4352 + r * 136 + c16 * 4) * 4u,
                    xb + (size_t)(kc * 32 + 32 + r) * N_PIX + px0 + c16 * 4);
            }
            CP_COMMIT();
        }

        const float* xc = sm + K1_XS + buf * 4352;
#pragma unroll
        for (int ks4 = 0; ks4 < 4; ks4++) {
            const int kr = ks4 * 8;
            // B fragments (x), tf32-rounded at load
            uint32_t b00 = tf32u(xc[(kr + tig)     * 136 + nA + g]);
            uint32_t b01 = tf32u(xc[(kr + tig + 4) * 136 + nA + g]);
            uint32_t b10 = tf32u(xc[(kr + tig)     * 136 + nA + 8 + g]);
            uint32_t b11 = tf32u(xc[(kr + tig + 4) * 136 + nA + 8 + g]);
            const int kcol = kc * 32 + kr + tig;
#pragma unroll
            for (int mt = 0; mt < 6; mt++) {
                const float* ar = sW + (mt * 16 + g) * 132 + kcol;
                uint32_t a0 = __float_as_uint(ar[0]);
                uint32_t a1 = __float_as_uint(ar[8 * 132]);
                uint32_t a2 = __float_as_uint(ar[4]);
                uint32_t a3 = __float_as_uint(ar[8 * 132 + 4]);
                MMA_TF32((&dd[mt][0]), a0, a1, a2, a3, b00, b01);
                MMA_TF32((&dd[mt][4]), a0, a1, a2, a3, b10, b11);
            }
        }
    }
    __syncthreads();                       // xs buffers dead -> pool scratch

    // ---- q (m-tile 0): write tf32-rounded fragments straight to gmem ----
#pragma unroll
    for (int nb = 0; nb < 2; nb++) {
        int n = nA + nb * 8 + 2 * tig;
        size_t qi0 = ((size_t)(b * 16 + g))     * N_PIX + px0 + n;
        size_t qi1 = ((size_t)(b * 16 + g + 8)) * N_PIX + px0 + n;
        *(float2*)&g_q[qi0] = make_float2(tf32r(dd[0][nb * 4]),     tf32r(dd[0][nb * 4 + 1]));
        *(float2*)&g_q[qi1] = make_float2(tf32r(dd[0][nb * 4 + 2]), tf32r(dd[0][nb * 4 + 3]));
    }

    // ---- k/v: horizontal max intra-thread, stash to pool scratch ----
    float* pb = sm + K1_XS;                // [80 ch][2 rows][34] = 5440 floats
#pragma unroll
    for (int mt = 1; mt < 6; mt++) {
#pragma unroll
        for (int nb = 0; nb < 2; nb++) {
            int n = nA + nb * 8 + 2 * tig;
            int rrow = n >> 6;             // image row within pair
            int wp = (n & 63) >> 1;        // pooled col
            int ch = mt * 16 - 16 + g;
            pb[ch * 68 + rrow * 34 + wp]       = fmaxf(dd[mt][nb * 4],     dd[mt][nb * 4 + 1]);
            pb[(ch + 8) * 68 + rrow * 34 + wp] = fmaxf(dd[mt][nb * 4 + 2], dd[mt][nb * 4 + 3]);
        }
    }
    __syncthreads();

    // ---- vertical max + store k (tf32) / v (bf16) ----
    const int mbase = blockIdx.x * 32;
    for (int i = t; i < 2560; i += 256) {
        int ch = i >> 5, wp = i & 31;
        float r = fmaxf(pb[ch * 68 + wp], pb[ch * 68 + 34 + wp]);
        if (ch < 16) g_k[((b * 16 + ch) << 10) + mbase + wp] = tf32r(r);
        else         g_v[((b * 64 + ch - 16) << 10) + mbase + wp] = __float2bfloat16_rn(r);
    }
}

// ---------------------------------------------------------------------------
// Kernel 2: fully-tensorized fused attention (unchanged from R10, 116us).
// ---------------------------------------------------------------------------
#define SV_OFF(buf)  ((buf) ? 4352u : 0u)
#define SK_OFF(buf)  (8704u + ((buf) ? 2176u : 0u))
#define SP_OFF       13056u
#define SQ_OFF       15232u
#define SSUM_OFF     15760u
#define SINV_OFF     15920u
#define SMEM2_FLOATS 15952

__device__ __forceinline__ void stage_chunk(
    uint32_t sbase, int buf, int chk, int t,
    const float4* __restrict__ gk4, const __nv_bfloat16* __restrict__ gvb)
{
    uint32_t kdst = sbase + SK_OFF(buf) * 4u;
    uint32_t vdst = sbase + SV_OFF(buf) * 4u;
#pragma unroll
    for (int q = 0; q < 2; q++) {
        int i = t + q * 256;
        int r = i >> 5, c = i & 31;
        CPA(kdst + (uint32_t)r * 544u + (uint32_t)c * 16u, gk4 + r * 256 + chk * 32 + c);
    }
#pragma unroll
    for (int q = 0; q < 4; q++) {
        int i = t + q * 256;
        int r = i >> 4, c8 = i & 15;
        CPA(vdst + (uint32_t)r * 272u + (uint32_t)c8 * 16u,
            gvb + ((size_t)r << 10) + chk * 128 + c8 * 8);
    }
}

__global__ __launch_bounds__(256, 2) void attn_kernel(
    const float* __restrict__ x,
    const float* __restrict__ wo,
    const float* __restrict__ gamma,
    float* __restrict__ out)
{
    extern __shared__ float sm[];
    float* sQ   = sm + SQ_OFF;
    float* sSum = sm + SSUM_OFF;
    float* sInv = sm + SINV_OFF;
    __nv_bfloat16* sP16 = (__nv_bfloat16*)(sm + SP_OFF);

    const int t    = threadIdx.x;
    const int w    = t >> 5;
    const int lane = t & 31;
    const int b    = blockIdx.y;
    const int n0   = blockIdx.x * 32;

    const int g   = lane >> 2;
    const int tig = lane & 3;
    const int nh  = (w & 1) * 16;
    const int mq  = (w >> 1) * 32;
    const int cA0 = (w >> 1) * 16;
    const int nwb = (w & 1) * 16;
    const int o0  = w * 16;

    const uint32_t sbase = (uint32_t)__cvta_generic_to_shared(sm);
    const float4* gk4 = (const float4*)(g_k + b * 16 * M_PIX);
    const __nv_bfloat16* gvb = g_v + (size_t)b * 64 * M_PIX;

    const int matI = lane >> 3, ii = lane & 7;
    const uint32_t aRowOff = (uint32_t)(cA0 + ii + 8 * (matI & 1)) * 272u
                           + (uint32_t)(matI >> 1) * 16u;
    const uint32_t bAddr   = sbase + SP_OFF * 4u
                           + (uint32_t)(nwb + ii + 8 * (matI >> 1)) * 272u
                           + (uint32_t)(matI & 1) * 16u;

    stage_chunk(sbase, 0, 0, t, gk4, gvb);
    CP_COMMIT();
    for (int i = t; i < 512; i += 256) {
        int dd = i >> 5, j = i & 31;
        sQ[dd * 33 + j] = g_q[(b * 16 + dd) * N_PIX + n0 + j];
    }
    __syncthreads();

    uint32_t qa[2][4];
#pragma unroll
    for (int ks = 0; ks < 2; ks++) {
        qa[ks][0] = __float_as_uint(sQ[(ks * 8 + tig)     * 33 + nh + g]);
        qa[ks][1] = __float_as_uint(sQ[(ks * 8 + tig)     * 33 + nh + g + 8]);
        qa[ks][2] = __float_as_uint(sQ[(ks * 8 + tig + 4) * 33 + nh + g]);
        qa[ks][3] = __float_as_uint(sQ[(ks * 8 + tig + 4) * 33 + nh + g + 8]);
    }

    float d0[4] = {0.f, 0.f, 0.f, 0.f};
    float d1[4] = {0.f, 0.f, 0.f, 0.f};
    float rs0 = 0.f, rs1 = 0.f;

    for (int chk = 0; chk < 8; chk++) {
        const int buf = chk & 1;
        const float* sK = sm + SK_OFF(buf);

        CP_WAIT0();
        __syncthreads();

        if (chk < 7) {
            stage_chunk(sbase, buf ^ 1, chk + 1, t, gk4, gvb);
            CP_COMMIT();
        }

        float sd[4][4];
#pragma unroll
        for (int j = 0; j < 4; j++)
#pragma unroll
            for (int k = 0; k < 4; k++) sd[j][k] = 0.f;

#pragma unroll
        for (int ks = 0; ks < 2; ks++) {
#pragma unroll
            for (int j = 0; j < 4; j++) {
                uint32_t b0 = __float_as_uint(sK[(ks * 8 + tig)     * 136 + mq + 8 * j + g]);
                uint32_t b1 = __float_as_uint(sK[(ks * 8 + tig + 4) * 136 + mq + 8 * j + g]);
                MMA_TF32(sd[j], qa[ks][0], qa[ks][1], qa[ks][2], qa[ks][3], b0, b1);
            }
        }

#pragma unroll
        for (int j = 0; j < 4; j++) {
            __nv_bfloat162 h0 = __float22bfloat162_rn(
                make_float2(__expf(sd[j][0]), __expf(sd[j][1])));
            __nv_bfloat162 h1 = __float22bfloat162_rn(
                make_float2(__expf(sd[j][2]), __expf(sd[j][3])));
            rs0 += __low2float(h0) + __high2float(h0);
            rs1 += __low2float(h1) + __high2float(h1);
            int mcol = mq + 8 * j + 2 * tig;
            *(uint32_t*)(sP16 + (nh + g)     * 136 + mcol) = *reinterpret_cast<uint32_t*>(&h0);
            *(uint32_t*)(sP16 + (nh + g + 8) * 136 + mcol) = *reinterpret_cast<uint32_t*>(&h1);
        }
        __syncthreads();

        {
            const uint32_t aBase = sbase + SV_OFF(buf) * 4u + aRowOff;
#pragma unroll
            for (int ks = 0; ks < 8; ks++) {
                uint32_t a0, a1, a2, a3, b0, b1, b2, b3;
                LDMX4(a0, a1, a2, a3, aBase + (uint32_t)ks * 32u);
                LDMX4(b0, b1, b2, b3, bAddr + (uint32_t)ks * 32u);
                MMA_BF16(d0, a0, a1, a2, a3, b0, b1);
                MMA_BF16(d1, a0, a1, a2, a3, b2, b3);
            }
        }
    }
    __syncthreads();

    float* sO = sm + 8704;
    {
        int cn = nwb + 2 * tig;
        sO[(cA0 + g)     * 40 + cn]     = tf32r(d0[0]);
        sO[(cA0 + g)     * 40 + cn + 1] = tf32r(d0[1]);
        sO[(cA0 + g + 8) * 40 + cn]     = tf32r(d0[2]);
        sO[(cA0 + g + 8) * 40 + cn + 1] = tf32r(d0[3]);
        sO[(cA0 + g)     * 40 + cn + 8] = tf32r(d1[0]);
        sO[(cA0 + g)     * 40 + cn + 9] = tf32r(d1[1]);
        sO[(cA0 + g + 8) * 40 + cn + 8] = tf32r(d1[2]);
        sO[(cA0 + g + 8) * 40 + cn + 9] = tf32r(d1[3]);
    }
    rs0 += __shfl_xor_sync(0xffffffffu, rs0, 1);
    rs0 += __shfl_xor_sync(0xffffffffu, rs0, 2);
    rs1 += __shfl_xor_sync(0xffffffffu, rs1, 1);
    rs1 += __shfl_xor_sync(0xffffffffu, rs1, 2);
    if (tig == 0) {
        sSum[(nh + g)     * 5 + (w >> 1)] = rs0;
        sSum[(nh + g + 8) * 5 + (w >> 1)] = rs1;
    }
    float* sWo = sm;
    for (int i = t; i < 8192; i += 256) {
        int o = i >> 6, c = i & 63;
        sWo[c * 136 + o] = tf32r(wo[i]);
    }
    __syncthreads();

    if (t < 32) {
        float s = sSum[t * 5] + sSum[t * 5 + 1] + sSum[t * 5 + 2] + sSum[t * 5 + 3];
        sInv[t] = 1.f / s;
    }
    __syncthreads();

    {
        float od[4][4];
#pragma unroll
        for (int j = 0; j < 4; j++)
#pragma unroll
            for (int k = 0; k < 4; k++) od[j][k] = 0.f;

#pragma unroll
        for (int ks = 0; ks < 8; ks++) {
            uint32_t a0 = __float_as_uint(sWo[(8 * ks + tig)     * 136 + o0 + g]);
            uint32_t a1 = __float_as_uint(sWo[(8 * ks + tig)     * 136 + o0 + g + 8]);
            uint32_t a2 = __float_as_uint(sWo[(8 * ks + tig + 4) * 136 + o0 + g]);
            uint32_t a3 = __float_as_uint(sWo[(8 * ks + tig + 4) * 136 + o0 + g + 8]);
#pragma unroll
            for (int j = 0; j < 4; j++) {
                uint32_t b0 = __float_as_uint(sO[(8 * ks + tig)     * 40 + 8 * j + g]);
                uint32_t b1 = __float_as_uint(sO[(8 * ks + tig + 4) * 40 + 8 * j + g]);
                MMA_TF32(od[j], a0, a1, a2, a3, b0, b1);
            }
        }

        const float gm = gamma[0];
#pragma unroll
        for (int j = 0; j < 4; j++) {
            int nn = 8 * j + 2 * tig;
            float s0 = gm * sInv[nn];
            float s1 = gm * sInv[nn + 1];
            size_t gi0 = ((size_t)(b * 128 + o0 + g)) * N_PIX + n0 + nn;
            size_t gi1 = ((size_t)(b * 128 + o0 + g + 8)) * N_PIX + n0 + nn;
            float2 x0 = *(const float2*)&x[gi0];
            float2 x1 = *(const float2*)&x[gi1];
            float2 r0, r1;
            r0.x = fmaf(s0, od[j][0], x0.x);
            r0.y = fmaf(s1, od[j][1], x0.y);
            r1.x = fmaf(s0, od[j][2], x1.x);
            r1.y = fmaf(s1, od[j][3], x1.y);
            *(float2*)&out[gi0] = r0;
            *(float2*)&out[gi1] = r1;
        }
    }
}

// ---------------------------------------------------------------------------
extern "C" void kernel_launch(void* const* d_in, const int* in_sizes, int n_in,
                              void* d_out, int out_size)
{
    const float* x     = (const float*)d_in[0];
    const float* wq    = (const float*)d_in[1];
    const float* wk    = (const float*)d_in[2];
    const float* wv    = (const float*)d_in[3];
    const float* wo    = (const float*)d_in[4];
    const float* gamma = (const float*)d_in[5];
    float* out = (float*)d_out;

    const int smem1 = K1_SMEM * 4;        // 85504
    const int smem2 = SMEM2_FLOATS * 4;   // 63808

    cudaFuncSetAttribute(proj_pool_kernel, cudaFuncAttributeMaxDynamicSharedMemorySize, smem1);
    cudaFuncSetAttribute(attn_kernel,      cudaFuncAttributeMaxDynamicSharedMemorySize, smem2);

    proj_pool_kernel<<<dim3(32, 16), 256, smem1>>>(x, wq, wk, wv);
    attn_kernel<<<dim3(128, 16), 256, smem2>>>(x, wo, gamma, out);
}

// round 12
// speedup vs baseline: 4.8952x; 1.5302x over previous
#include <cuda_runtime.h>
#include <cuda_bf16.h>
#include <cstdint>

#define N_PIX 4096
#define M_PIX 1024

// cp.async helpers (16B per op)
#define CPA(dst32, srcp) \
    asm volatile("cp.async.ca.shared.global [%0], [%1], 16;" :: "r"(dst32), "l"(srcp) : "memory")
#define CP_COMMIT() asm volatile("cp.async.commit_group;" ::: "memory")
#define CP_WAIT0()  asm volatile("cp.async.wait_group 0;" ::: "memory")

// ldmatrix x4 (b16), per-lane row addressing
#define LDMX4(r0, r1, r2, r3, addr) \
    asm volatile("ldmatrix.sync.aligned.m8n8.x4.shared.b16 {%0,%1,%2,%3}, [%4];" \
        : "=r"(r0), "=r"(r1), "=r"(r2), "=r"(r3) : "r"(addr))

// m16n8k16 bf16 MMA, fp32 accumulate
#define MMA_BF16(d, a0, a1, a2, a3, b0, b1) \
    asm volatile("mma.sync.aligned.m16n8k16.row.col.f32.bf16.bf16.f32 " \
        "{%0,%1,%2,%3}, {%4,%5,%6,%7}, {%8,%9}, {%0,%1,%2,%3};" \
        : "+f"(d[0]), "+f"(d[1]), "+f"(d[2]), "+f"(d[3]) \
        : "r"(a0), "r"(a1), "r"(a2), "r"(a3), "r"(b0), "r"(b1))

// m16n8k8 tf32 MMA, fp32 accumulate
#define MMA_TF32(d, a0, a1, a2, a3, b0, b1) \
    asm volatile("mma.sync.aligned.m16n8k8.row.col.f32.tf32.tf32.f32 " \
        "{%0,%1,%2,%3}, {%4,%5,%6,%7}, {%8,%9}, {%0,%1,%2,%3};" \
        : "+f"(d[0]), "+f"(d[1]), "+f"(d[2]), "+f"(d[3]) \
        : "r"(a0), "r"(a1), "r"(a2), "r"(a3), "r"(b0), "r"(b1))

// tf32 round-to-nearest
__device__ __forceinline__ float tf32r(float f) {
    uint32_t u;
    asm("cvt.rna.tf32.f32 %0, %1;" : "=r"(u) : "f"(f));
    return __uint_as_float(u);
}
__device__ __forceinline__ uint32_t pkbf(float a, float b) {
    __nv_bfloat162 h = __float22bfloat162_rn(make_float2(a, b));
    return *reinterpret_cast<uint32_t*>(&h);
}
__device__ __forceinline__ float sum2bf(uint32_t p) {
    __nv_bfloat162 h = *reinterpret_cast<__nv_bfloat162*>(&p);
    float2 f = __bfloat1622float2(h);
    return f.x + f.y;
}

// Scratch (device globals — no allocation allowed)
__device__ __align__(16) float         g_q[16 * 16 * N_PIX];   // [b][16][n] fp32
__device__ __align__(16) __nv_bfloat16 g_k[16 * M_PIX * 16];   // [b][m][16] bf16
__device__ __align__(16) __nv_bfloat16 g_v[16 * 64 * M_PIX];   // [b][64][m] bf16

// ---------------------------------------------------------------------------
// Kernel 1 (tensorized, as R11): out[96][128px] = W*x on tf32 MMA, 2x2 pool.
// K now stored bf16 [m][16], Q plain fp32, V bf16.
// ---------------------------------------------------------------------------
#define K1_XS   12672
#define K1_SMEM (12672 + 2 * 4352)

__global__ __launch_bounds__(256, 2) void proj_pool_kernel(
    const float* __restrict__ x,
    const float* __restrict__ wq,
    const float* __restrict__ wk,
    const float* __restrict__ wv)
{
    extern __shared__ float sm[];
    float* sW = sm;                  // 96 x 132
    const int t    = threadIdx.x;
    const int lane = t & 31;
    const int w    = t >> 5;
    const int g    = lane >> 2;
    const int tig  = lane & 3;
    const int b    = blockIdx.y;
    const int px0  = blockIdx.x * 128;

    const float* xb = x + (size_t)b * 128 * N_PIX;
    const uint32_t sbase = (uint32_t)__cvta_generic_to_shared(sm);

#pragma unroll
    for (int q = 0; q < 4; q++) {
        int i = t + q * 256;
        int r = i >> 5, c16 = i & 31;
        CPA(sbase + (uint32_t)(K1_XS + r * 136 + c16 * 4) * 4u,
            xb + (size_t)r * N_PIX + px0 + c16 * 4);
    }
    CP_COMMIT();

    for (int i = t; i < 12288; i += 256) {
        int o = i >> 7, c = i & 127;
        float wv_;
        if (o < 16)      wv_ = wq[i];
        else if (o < 32) wv_ = wk[i - 2048];
        else             wv_ = wv[i - 4096];
        sW[o * 132 + c] = tf32r(wv_);
    }

    float dd[6][8];
#pragma unroll
    for (int mt = 0; mt < 6; mt++)
#pragma unroll
        for (int j = 0; j < 8; j++) dd[mt][j] = 0.f;

    const int nA = w * 16;

#pragma unroll 1
    for (int kc = 0; kc < 4; kc++) {
        const int buf = kc & 1;
        CP_WAIT0();
        __syncthreads();

        if (kc < 3) {
#pragma unroll
            for (int q = 0; q < 4; q++) {
                int i = t + q * 256;
                int r = i >> 5, c16 = i & 31;
                CPA(sbase + (uint32_t)(K1_XS + (buf ^ 1) * 4352 + r * 136 + c16 * 4) * 4u,
                    xb + (size_t)(kc * 32 + 32 + r) * N_PIX + px0 + c16 * 4);
            }
            CP_COMMIT();
        }

        const float* xc = sm + K1_XS + buf * 4352;
#pragma unroll
        for (int ks4 = 0; ks4 < 4; ks4++) {
            const int kr = ks4 * 8;
            uint32_t b00, b01, b10, b11;
            {
                uint32_t u;
                asm("cvt.rna.tf32.f32 %0, %1;" : "=r"(u) : "f"(xc[(kr + tig)     * 136 + nA + g]));     b00 = u;
                asm("cvt.rna.tf32.f32 %0, %1;" : "=r"(u) : "f"(xc[(kr + tig + 4) * 136 + nA + g]));     b01 = u;
                asm("cvt.rna.tf32.f32 %0, %1;" : "=r"(u) : "f"(xc[(kr + tig)     * 136 + nA + 8 + g])); b10 = u;
                asm("cvt.rna.tf32.f32 %0, %1;" : "=r"(u) : "f"(xc[(kr + tig + 4) * 136 + nA + 8 + g])); b11 = u;
            }
            const int kcol = kc * 32 + kr + tig;
#pragma unroll
            for (int mt = 0; mt < 6; mt++) {
                const float* ar = sW + (mt * 16 + g) * 132 + kcol;
                uint32_t a0 = __float_as_uint(ar[0]);
                uint32_t a1 = __float_as_uint(ar[8 * 132]);
                uint32_t a2 = __float_as_uint(ar[4]);
                uint32_t a3 = __float_as_uint(ar[8 * 132 + 4]);
                MMA_TF32((&dd[mt][0]), a0, a1, a2, a3, b00, b01);
                MMA_TF32((&dd[mt][4]), a0, a1, a2, a3, b10, b11);
            }
        }
    }
    __syncthreads();

    // q: write fragments straight to gmem (fp32)
#pragma unroll
    for (int nb = 0; nb < 2; nb++) {
        int n = nA + nb * 8 + 2 * tig;
        size_t qi0 = ((size_t)(b * 16 + g))     * N_PIX + px0 + n;
        size_t qi1 = ((size_t)(b * 16 + g + 8)) * N_PIX + px0 + n;
        *(float2*)&g_q[qi0] = make_float2(dd[0][nb * 4],     dd[0][nb * 4 + 1]);
        *(float2*)&g_q[qi1] = make_float2(dd[0][nb * 4 + 2], dd[0][nb * 4 + 3]);
    }

    // k/v: horizontal max intra-thread -> pool scratch
    float* pb = sm + K1_XS;
#pragma unroll
    for (int mt = 1; mt < 6; mt++) {
#pragma unroll
        for (int nb = 0; nb < 2; nb++) {
            int n = nA + nb * 8 + 2 * tig;
            int rrow = n >> 6;
            int wp = (n & 63) >> 1;
            int ch = mt * 16 - 16 + g;
            pb[ch * 68 + rrow * 34 + wp]       = fmaxf(dd[mt][nb * 4],     dd[mt][nb * 4 + 1]);
            pb[(ch + 8) * 68 + rrow * 34 + wp] = fmaxf(dd[mt][nb * 4 + 2], dd[mt][nb * 4 + 3]);
        }
    }
    __syncthreads();

    const int mbase = blockIdx.x * 32;
    for (int i = t; i < 2560; i += 256) {
        int ch = i >> 5, wp = i & 31;
        float r = fmaxf(pb[ch * 68 + wp], pb[ch * 68 + 34 + wp]);
        if (ch < 16)
            g_k[((size_t)(b * M_PIX + mbase + wp)) * 16 + ch] = __float2bfloat16_rn(r);
        else
            g_v[((b * 64 + ch - 16) << 10) + mbase + wp] = __float2bfloat16_rn(r);
    }
}

// ---------------------------------------------------------------------------
// Kernel 2: FA2-style fused attention. CTA = 128 queries, 8 warps x 16q,
// full m in registers (P never hits smem). bf16 MMA for S and O; tf32 MMA
// epilogue. 256 threads, 2 CTAs/SM, cp.async double-buffered K/V staging.
// SMEM (floats): sV[2] bf16 64x136 (4352 each), sK[2] bf16 128x24 (1536 each),
// then epilogue aliases: sO f32 64x136 (8704 @0), sWo f32 64x136 (@8704),
// sSum 128 @17408, sInv 128 @17536. Total 17664 fl = 69.0KB.
// ---------------------------------------------------------------------------
#define SV_OFF(buf)  ((buf) ? 4352u : 0u)
#define SK_OFF(buf)  (8704u + ((buf) ? 1536u : 0u))
#define SO_OFF       0u
#define SWO_OFF      8704u
#define SSUM_OFF     17408u
#define SINV_OFF     17536u
#define SMEM2_FLOATS 17664

__device__ __forceinline__ void stage_chunk(
    uint32_t sbase, int buf, int chk, int t,
    const __nv_bfloat16* __restrict__ gkb, const __nv_bfloat16* __restrict__ gvb)
{
    uint32_t kdst = sbase + SK_OFF(buf) * 4u;
    uint32_t vdst = sbase + SV_OFF(buf) * 4u;
    {   // K chunk: [128 m][16 d] bf16, smem row stride 48B
        int m = t >> 1, h = t & 1;
        CPA(kdst + (uint32_t)m * 48u + (uint32_t)h * 16u,
            gkb + ((size_t)(chk * 128 + m)) * 16 + h * 8);
    }
#pragma unroll
    for (int q = 0; q < 4; q++) {   // V chunk: [64 c][128 m] bf16, stride 272B
        int i = t + q * 256;
        int r = i >> 4, u = i & 15;
        CPA(vdst + (uint32_t)r * 272u + (uint32_t)u * 16u,
            gvb + ((size_t)r << 10) + chk * 128 + u * 8);
    }
}

__global__ __launch_bounds__(256, 2) void attn_kernel(
    const float* __restrict__ x,
    const float* __restrict__ wo,
    const float* __restrict__ gamma,
    float* __restrict__ out)
{
    extern __shared__ float sm[];
    float* sSum = sm + SSUM_OFF;
    float* sInv = sm + SINV_OFF;

    const int t    = threadIdx.x;
    const int w    = t >> 5;
    const int lane = t & 31;
    const int b    = blockIdx.y;
    const int n0   = blockIdx.x * 128;

    const int g    = lane >> 2;
    const int tig  = lane & 3;
    const int nw   = w * 16;          // warp's query-tile base (within CTA)
    const int matI = lane >> 3, ii = lane & 7;

    const uint32_t sbase = (uint32_t)__cvta_generic_to_shared(sm);
    const __nv_bfloat16* gkb = g_k + (size_t)b * M_PIX * 16;
    const __nv_bfloat16* gvb = g_v + (size_t)b * 64 * M_PIX;

    // per-lane ldmatrix offsets
    const uint32_t kOff = (uint32_t)(ii + 8 * (matI >> 1)) * 48u + (uint32_t)(matI & 1) * 16u;
    const uint32_t vOff = (uint32_t)(ii + 8 * (matI >> 1)) * 272u + (uint32_t)(matI & 1) * 16u;

    // prologue: stage chunk 0; build Q A-fragments (bf16) from gmem
    stage_chunk(sbase, 0, 0, t, gkb, gvb);
    CP_COMMIT();

    uint32_t qa0, qa1, qa2, qa3;
    {
        const float* gq = g_q + (size_t)b * 16 * N_PIX + n0;
        int nq = nw + g;
        qa0 = pkbf(gq[(2 * tig)     * N_PIX + nq],     gq[(2 * tig + 1) * N_PIX + nq]);
        qa1 = pkbf(gq[(2 * tig)     * N_PIX + nq + 8], gq[(2 * tig + 1) * N_PIX + nq + 8]);
        qa2 = pkbf(gq[(2 * tig + 8) * N_PIX + nq],     gq[(2 * tig + 9) * N_PIX + nq]);
        qa3 = pkbf(gq[(2 * tig + 8) * N_PIX + nq + 8], gq[(2 * tig + 9) * N_PIX + nq + 8]);
    }

    float oc[8][4];
#pragma unroll
    for (int i = 0; i < 8; i++)
#pragma unroll
        for (int j = 0; j < 4; j++) oc[i][j] = 0.f;
    float rs0 = 0.f, rs1 = 0.f;

#pragma unroll 1
    for (int chk = 0; chk < 8; chk++) {
        const int buf = chk & 1;

        CP_WAIT0();
        __syncthreads();   // chunk chk visible; all warps done with previous buf

        if (chk < 7) {
            stage_chunk(sbase, buf ^ 1, chk + 1, t, gkb, gvb);
            CP_COMMIT();
        }

        const uint32_t kBase = sbase + SK_OFF(buf) * 4u + kOff;
        const uint32_t vBase = sbase + SV_OFF(buf) * 4u + vOff;

#pragma unroll
        for (int h = 0; h < 2; h++) {
            // ---- S half: 16q x 64m on bf16 MMA ----
            float sd[8][4];
#pragma unroll
            for (int j = 0; j < 8; j++)
#pragma unroll
                for (int k = 0; k < 4; k++) sd[j][k] = 0.f;

#pragma unroll
            for (int u = 0; u < 4; u++) {
                uint32_t k0, k1, k2, k3;
                LDMX4(k0, k1, k2, k3, kBase + (uint32_t)(4 * h + u) * 768u);
                MMA_BF16(sd[2 * u],     qa0, qa1, qa2, qa3, k0, k1);
                MMA_BF16(sd[2 * u + 1], qa0, qa1, qa2, qa3, k2, k3);
            }

            // ---- exp + bf16 pack (P stays in registers as A-fragments) ----
            uint32_t pa[4][4];
#pragma unroll
            for (int j = 0; j < 4; j++) {
                uint32_t h00 = pkbf(__expf(sd[2 * j][0]),     __expf(sd[2 * j][1]));
                uint32_t h01 = pkbf(__expf(sd[2 * j][2]),     __expf(sd[2 * j][3]));
                uint32_t h10 = pkbf(__expf(sd[2 * j + 1][0]), __expf(sd[2 * j + 1][1]));
                uint32_t h11 = pkbf(__expf(sd[2 * j + 1][2]), __expf(sd[2 * j + 1][3]));
                rs0 += sum2bf(h00) + sum2bf(h10);
                rs1 += sum2bf(h01) + sum2bf(h11);
                pa[j][0] = h00; pa[j][1] = h01; pa[j][2] = h10; pa[j][3] = h11;
            }

            // ---- O half: O^T[16q][64c] += P * V^T on bf16 MMA ----
#pragma unroll
            for (int kt = 0; kt < 4; kt++) {
                const uint32_t colb = (uint32_t)(4 * h + kt) * 32u;
#pragma unroll
                for (int cp = 0; cp < 4; cp++) {
                    uint32_t v0, v1, v2, v3;
                    LDMX4(v0, v1, v2, v3, vBase + (uint32_t)cp * 4352u + colb);
                    MMA_BF16(oc[2 * cp],     pa[kt][0], pa[kt][1], pa[kt][2], pa[kt][3], v0, v1);
                    MMA_BF16(oc[2 * cp + 1], pa[kt][0], pa[kt][1], pa[kt][2], pa[kt][3], v2, v3);
                }
            }
        }
    }
    __syncthreads();   // all smem reads done; alias to epilogue layout

    // ---- write O^T fragments tf32-rounded to sO[c][n] (stride 136) ----
    float* sO = sm + SO_OFF;
#pragma unroll
    for (int ct = 0; ct < 8; ct++) {
        int c = 8 * ct + 2 * tig;
        sO[c * 136 + nw + g]           = tf32r(oc[ct][0]);
        sO[(c + 1) * 136 + nw + g]     = tf32r(oc[ct][1]);
        sO[c * 136 + nw + g + 8]       = tf32r(oc[ct][2]);
        sO[(c + 1) * 136 + nw + g + 8] = tf32r(oc[ct][3]);
    }
    // rowsums: reduce over tig (m-split within row), store per query row
    rs0 += __shfl_xor_sync(0xffffffffu, rs0, 1);
    rs0 += __shfl_xor_sync(0xffffffffu, rs0, 2);
    rs1 += __shfl_xor_sync(0xffffffffu, rs1, 1);
    rs1 += __shfl_xor_sync(0xffffffffu, rs1, 2);
    if (tig == 0) {
        sSum[nw + g]     = rs0;
        sSum[nw + g + 8] = rs1;
    }
    // stage wo tf32-rounded as sWo[c][o] (stride 136)
    float* sWo = sm + SWO_OFF;
    for (int i = t; i < 8192; i += 256) {
        int o = i >> 6, c = i & 63;
        sWo[c * 136 + o] = tf32r(wo[i]);
    }
    __syncthreads();

    if (t < 128) sInv[t] = 1.f / sSum[t];
    __syncthreads();

    // ---- epilogue on tf32 MMA: out[o][n] = gamma*inv[n]*(wo.O)[o][n] + x ----
    {
        const int o0 = w * 16;
        float od[16][4];
#pragma unroll
        for (int j = 0; j < 16; j++)
#pragma unroll
            for (int k = 0; k < 4; k++) od[j][k] = 0.f;

#pragma unroll
        for (int ks = 0; ks < 8; ks++) {
            uint32_t a0 = __float_as_uint(sWo[(8 * ks + tig)     * 136 + o0 + g]);
            uint32_t a1 = __float_as_uint(sWo[(8 * ks + tig)     * 136 + o0 + g + 8]);
            uint32_t a2 = __float_as_uint(sWo[(8 * ks + tig + 4) * 136 + o0 + g]);
            uint32_t a3 = __float_as_uint(sWo[(8 * ks + tig + 4) * 136 + o0 + g + 8]);
#pragma unroll
            for (int nt = 0; nt < 16; nt++) {
                uint32_t b0 = __float_as_uint(sO[(8 * ks + tig)     * 136 + 8 * nt + g]);
                uint32_t b1 = __float_as_uint(sO[(8 * ks + tig + 4) * 136 + 8 * nt + g]);
                MMA_TF32(od[nt], a0, a1, a2, a3, b0, b1);
            }
        }

        const float gm = gamma[0];
#pragma unroll
        for (int nt = 0; nt < 16; nt++) {
            int nn = 8 * nt + 2 * tig;
            float s0 = gm * sInv[nn];
            float s1 = gm * sInv[nn + 1];
            size_t gi0 = ((size_t)(b * 128 + o0 + g)) * N_PIX + n0 + nn;
            size_t gi1 = ((size_t)(b * 128 + o0 + g + 8)) * N_PIX + n0 + nn;
            float2 x0 = *(const float2*)&x[gi0];
            float2 x1 = *(const float2*)&x[gi1];
            float2 r0, r1;
            r0.x = fmaf(s0, od[nt][0], x0.x);
            r0.y = fmaf(s1, od[nt][1], x0.y);
            r1.x = fmaf(s0, od[nt][2], x1.x);
            r1.y = fmaf(s1, od[nt][3], x1.y);
            *(float2*)&out[gi0] = r0;
            *(float2*)&out[gi1] = r1;
        }
    }
}

// ---------------------------------------------------------------------------
extern "C" void kernel_launch(void* const* d_in, const int* in_sizes, int n_in,
                              void* d_out, int out_size)
{
    const float* x     = (const float*)d_in[0];
    const float* wq    = (const float*)d_in[1];
    const float* wk    = (const float*)d_in[2];
    const float* wv    = (const float*)d_in[3];
    const float* wo    = (const float*)d_in[4];
    const float* gamma = (const float*)d_in[5];
    float* out = (float*)d_out;

    const int smem1 = K1_SMEM * 4;        // 85504
    const int smem2 = SMEM2_FLOATS * 4;   // 70656

    cudaFuncSetAttribute(proj_pool_kernel, cudaFuncAttributeMaxDynamicSharedMemorySize, smem1);
    cudaFuncSetAttribute(attn_kernel,      cudaFuncAttributeMaxDynamicSharedMemorySize, smem2);

    proj_pool_kernel<<<dim3(32, 16), 256, smem1>>>(x, wq, wk, wv);
    attn_kernel<<<dim3(32, 16), 256, smem2>>>(x, wo, gamma, out);
}

// round 13
// speedup vs baseline: 5.2529x; 1.0731x over previous
#include <cuda_runtime.h>
#include <cuda_bf16.h>
#include <cstdint>

#define N_PIX 4096
#define M_PIX 1024

// cp.async helpers (16B per op)
#define CPA(dst32, srcp) \
    asm volatile("cp.async.ca.shared.global [%0], [%1], 16;" :: "r"(dst32), "l"(srcp) : "memory")
#define CP_COMMIT() asm volatile("cp.async.commit_group;" ::: "memory")
#define CP_WAIT0()  asm volatile("cp.async.wait_group 0;" ::: "memory")

// ldmatrix x4 (b16)
#define LDMX4(r0, r1, r2, r3, addr) \
    asm volatile("ldmatrix.sync.aligned.m8n8.x4.shared.b16 {%0,%1,%2,%3}, [%4];" \
        : "=r"(r0), "=r"(r1), "=r"(r2), "=r"(r3) : "r"(addr))
#define LDMX4T(r0, r1, r2, r3, addr) \
    asm volatile("ldmatrix.sync.aligned.m8n8.x4.trans.shared.b16 {%0,%1,%2,%3}, [%4];" \
        : "=r"(r0), "=r"(r1), "=r"(r2), "=r"(r3) : "r"(addr))

// m16n8k16 bf16 MMA, fp32 accumulate
#define MMA_BF16(d, a0, a1, a2, a3, b0, b1) \
    asm volatile("mma.sync.aligned.m16n8k16.row.col.f32.bf16.bf16.f32 " \
        "{%0,%1,%2,%3}, {%4,%5,%6,%7}, {%8,%9}, {%0,%1,%2,%3};" \
        : "+f"(d[0]), "+f"(d[1]), "+f"(d[2]), "+f"(d[3]) \
        : "r"(a0), "r"(a1), "r"(a2), "r"(a3), "r"(b0), "r"(b1))

// m16n8k8 tf32 MMA, fp32 accumulate
#define MMA_TF32(d, a0, a1, a2, a3, b0, b1) \
    asm volatile("mma.sync.aligned.m16n8k8.row.col.f32.tf32.tf32.f32 " \
        "{%0,%1,%2,%3}, {%4,%5,%6,%7}, {%8,%9}, {%0,%1,%2,%3};" \
        : "+f"(d[0]), "+f"(d[1]), "+f"(d[2]), "+f"(d[3]) \
        : "r"(a0), "r"(a1), "r"(a2), "r"(a3), "r"(b0), "r"(b1))

// tf32 round-to-nearest
__device__ __forceinline__ float tf32r(float f) {
    uint32_t u;
    asm("cvt.rna.tf32.f32 %0, %1;" : "=r"(u) : "f"(f));
    return __uint_as_float(u);
}
__device__ __forceinline__ uint32_t pkbf(float a, float b) {
    __nv_bfloat162 h = __float22bfloat162_rn(make_float2(a, b));
    return *reinterpret_cast<uint32_t*>(&h);
}
__device__ __forceinline__ float sum2bf(uint32_t p) {
    __nv_bfloat162 h = *reinterpret_cast<__nv_bfloat162*>(&p);
    float2 f = __bfloat1622float2(h);
    return f.x + f.y;
}

// Scratch (device globals — no allocation allowed)
__device__ __align__(16) float         g_q[16 * 16 * N_PIX];   // [b][16][n] fp32
__device__ __align__(16) __nv_bfloat16 g_k[16 * M_PIX * 16];   // [b][m][16] bf16
__device__ __align__(16) __nv_bfloat16 g_v[16 * 64 * M_PIX];   // [b][64][m] bf16

// ---------------------------------------------------------------------------
// Kernel 1 (bf16-tensorized): out[96][128px] = W*x on bf16 MMA + ldmatrix,
// then 2x2 maxpool. CTA = 128px = 2 rows, 8 warps x 16px. x streamed in 4
// k-chunks of 32 channels (cp.async fp32, converted to a single bf16 buffer
// per chunk); W staged once as bf16 [o][c] stride 136 (A-frags, straight
// LDSM); x B-frags via ldmatrix.trans on [c][px].
// ---------------------------------------------------------------------------
#define K1_W    0        // bf16 96x136 = 6528 fl
#define K1_X0   6528     // fp32 32x136
#define K1_X1   10880    // fp32 32x136
#define K1_XB   15232    // bf16 32x136 = 2176 fl
#define K1_SMEM 17408    // floats = 69632 B

__global__ __launch_bounds__(256, 2) void proj_pool_kernel(
    const float* __restrict__ x,
    const float* __restrict__ wq,
    const float* __restrict__ wk,
    const float* __restrict__ wv)
{
    extern __shared__ float sm[];
    __nv_bfloat16* sWb  = (__nv_bfloat16*)(sm + K1_W);    // [96][136]
    __nv_bfloat16* xb16 = (__nv_bfloat16*)(sm + K1_XB);   // [32][136]

    const int t    = threadIdx.x;
    const int lane = t & 31;
    const int w    = t >> 5;
    const int g    = lane >> 2;
    const int tig  = lane & 3;
    const int b    = blockIdx.y;
    const int px0  = blockIdx.x * 128;

    const float* xb = x + (size_t)b * 128 * N_PIX;
    const uint32_t sbase = (uint32_t)__cvta_generic_to_shared(sm);

    // ---- stage x chunk 0 (channels 0..31), fp32 ----
#pragma unroll
    for (int q = 0; q < 4; q++) {
        int i = t + q * 256;
        int r = i >> 5, c16 = i & 31;
        CPA(sbase + (uint32_t)(K1_X0 + r * 136 + c16 * 4) * 4u,
            xb + (size_t)r * N_PIX + px0 + c16 * 4);
    }
    CP_COMMIT();

    // ---- stage W bf16 [o][c] stride 136 ----
    for (int i = t; i < 6144; i += 256) {
        int o = i >> 6, c2 = i & 63;
        const float* src = (o < 16) ? (wq + o * 128)
                         : (o < 32) ? (wk + (o - 16) * 128)
                                    : (wv + (o - 32) * 128);
        *(uint32_t*)(sWb + o * 136 + 2 * c2) = pkbf(src[2 * c2], src[2 * c2 + 1]);
    }

    float dd[6][8];
#pragma unroll
    for (int mt = 0; mt < 6; mt++)
#pragma unroll
        for (int j = 0; j < 8; j++) dd[mt][j] = 0.f;

    const int nA   = w * 16;
    const int matI = lane >> 3, ii = lane & 7;
    // A (W) per-lane offset: row = mt*16 + ii + 8*(matI&1), k-16B block = matI>>1
    const uint32_t aOff = (uint32_t)(ii + 8 * (matI & 1)) * 272u + (uint32_t)(matI >> 1) * 16u;
    // B (x, trans) per-lane offset: stored row k = ii + 8*(matI&1), n-col = nA + 8*(matI>>1)
    const uint32_t bOff = (uint32_t)(ii + 8 * (matI & 1)) * 272u + (uint32_t)(nA + 8 * (matI >> 1)) * 2u;

#pragma unroll 1
    for (int kc = 0; kc < 4; kc++) {
        const int buf = kc & 1;
        CP_WAIT0();
        __syncthreads();               // chunk kc fp32 visible; prev MMA reads done

        if (kc < 3) {
#pragma unroll
            for (int q = 0; q < 4; q++) {
                int i = t + q * 256;
                int r = i >> 5, c16 = i & 31;
                CPA(sbase + (uint32_t)((buf ? K1_X0 : K1_X1) + r * 136 + c16 * 4) * 4u,
                    xb + (size_t)(kc * 32 + 32 + r) * N_PIX + px0 + c16 * 4);
            }
            CP_COMMIT();
        }

        // ---- convert fp32 chunk -> bf16 (single buffer) ----
        {
            const float* xs = sm + (buf ? K1_X1 : K1_X0);
            int r = t >> 3, c0 = (t & 7) * 16;
            float4 f0 = *(const float4*)&xs[r * 136 + c0];
            float4 f1 = *(const float4*)&xs[r * 136 + c0 + 4];
            float4 f2 = *(const float4*)&xs[r * 136 + c0 + 8];
            float4 f3 = *(const float4*)&xs[r * 136 + c0 + 12];
            uint4 u0, u1;
            u0.x = pkbf(f0.x, f0.y); u0.y = pkbf(f0.z, f0.w);
            u0.z = pkbf(f1.x, f1.y); u0.w = pkbf(f1.z, f1.w);
            u1.x = pkbf(f2.x, f2.y); u1.y = pkbf(f2.z, f2.w);
            u1.z = pkbf(f3.x, f3.y); u1.w = pkbf(f3.z, f3.w);
            *(uint4*)(xb16 + r * 136 + c0)     = u0;
            *(uint4*)(xb16 + r * 136 + c0 + 8) = u1;
        }
        __syncthreads();               // xb16 ready for all warps

        // ---- MMA: 2 k16-steps x 6 m-tiles x 2 n-tiles ----
        const uint32_t aB = sbase + aOff;          // sWb at offset 0
        const uint32_t bB = sbase + (uint32_t)K1_XB * 4u + bOff;
#pragma unroll
        for (int ks = 0; ks < 2; ks++) {
            uint32_t x0, x1, x2, x3;
            LDMX4T(x0, x1, x2, x3, bB + (uint32_t)ks * 16u * 272u);
#pragma unroll
            for (int mt = 0; mt < 6; mt++) {
                uint32_t a0, a1, a2, a3;
                LDMX4(a0, a1, a2, a3, aB + (uint32_t)(mt * 16) * 272u
                                         + (uint32_t)(kc * 64 + ks * 32));
                MMA_BF16((&dd[mt][0]), a0, a1, a2, a3, x0, x1);
                MMA_BF16((&dd[mt][4]), a0, a1, a2, a3, x2, x3);
            }
        }
    }
    __syncthreads();                   // x buffers dead -> pool scratch

    // ---- q (m-tile 0): write fragments straight to gmem (fp32) ----
#pragma unroll
    for (int nb = 0; nb < 2; nb++) {
        int n = nA + nb * 8 + 2 * tig;
        size_t qi0 = ((size_t)(b * 16 + g))     * N_PIX + px0 + n;
        size_t qi1 = ((size_t)(b * 16 + g + 8)) * N_PIX + px0 + n;
        *(float2*)&g_q[qi0] = make_float2(dd[0][nb * 4],     dd[0][nb * 4 + 1]);
        *(float2*)&g_q[qi1] = make_float2(dd[0][nb * 4 + 2], dd[0][nb * 4 + 3]);
    }

    // ---- k/v: horizontal max intra-thread -> pool scratch ----
    float* pb = sm + K1_X0;            // [80 ch][2 rows][34]
#pragma unroll
    for (int mt = 1; mt < 6; mt++) {
#pragma unroll
        for (int nb = 0; nb < 2; nb++) {
            int n = nA + nb * 8 + 2 * tig;
            int rrow = n >> 6;
            int wp = (n & 63) >> 1;
            int ch = mt * 16 - 16 + g;
            pb[ch * 68 + rrow * 34 + wp]       = fmaxf(dd[mt][nb * 4],     dd[mt][nb * 4 + 1]);
            pb[(ch + 8) * 68 + rrow * 34 + wp] = fmaxf(dd[mt][nb * 4 + 2], dd[mt][nb * 4 + 3]);
        }
    }
    __syncthreads();

    const int mbase = blockIdx.x * 32;
    for (int i = t; i < 2560; i += 256) {
        int ch = i >> 5, wp = i & 31;
        float r = fmaxf(pb[ch * 68 + wp], pb[ch * 68 + 34 + wp]);
        if (ch < 16)
            g_k[((size_t)(b * M_PIX + mbase + wp)) * 16 + ch] = __float2bfloat16_rn(r);
        else
            g_v[((b * 64 + ch - 16) << 10) + mbase + wp] = __float2bfloat16_rn(r);
    }
}

// ---------------------------------------------------------------------------
// Kernel 2: FA2-style fused attention (unchanged from R12, 64.9us).
// ---------------------------------------------------------------------------
#define SV_OFF(buf)  ((buf) ? 4352u : 0u)
#define SK_OFF(buf)  (8704u + ((buf) ? 1536u : 0u))
#define SO_OFF       0u
#define SWO_OFF      8704u
#define SSUM_OFF     17408u
#define SINV_OFF     17536u
#define SMEM2_FLOATS 17664

__device__ __forceinline__ void stage_chunk(
    uint32_t sbase, int buf, int chk, int t,
    const __nv_bfloat16* __restrict__ gkb, const __nv_bfloat16* __restrict__ gvb)
{
    uint32_t kdst = sbase + SK_OFF(buf) * 4u;
    uint32_t vdst = sbase + SV_OFF(buf) * 4u;
    {
        int m = t >> 1, h = t & 1;
        CPA(kdst + (uint32_t)m * 48u + (uint32_t)h * 16u,
            gkb + ((size_t)(chk * 128 + m)) * 16 + h * 8);
    }
#pragma unroll
    for (int q = 0; q < 4; q++) {
        int i = t + q * 256;
        int r = i >> 4, u = i & 15;
        CPA(vdst + (uint32_t)r * 272u + (uint32_t)u * 16u,
            gvb + ((size_t)r << 10) + chk * 128 + u * 8);
    }
}

__global__ __launch_bounds__(256, 2) void attn_kernel(
    const float* __restrict__ x,
    const float* __restrict__ wo,
    const float* __restrict__ gamma,
    float* __restrict__ out)
{
    extern __shared__ float sm[];
    float* sSum = sm + SSUM_OFF;
    float* sInv = sm + SINV_OFF;

    const int t    = threadIdx.x;
    const int w    = t >> 5;
    const int lane = t & 31;
    const int b    = blockIdx.y;
    const int n0   = blockIdx.x * 128;

    const int g    = lane >> 2;
    const int tig  = lane & 3;
    const int nw   = w * 16;
    const int matI = lane >> 3, ii = lane & 7;

    const uint32_t sbase = (uint32_t)__cvta_generic_to_shared(sm);
    const __nv_bfloat16* gkb = g_k + (size_t)b * M_PIX * 16;
    const __nv_bfloat16* gvb = g_v + (size_t)b * 64 * M_PIX;

    const uint32_t kOff = (uint32_t)(ii + 8 * (matI >> 1)) * 48u + (uint32_t)(matI & 1) * 16u;
    const uint32_t vOff = (uint32_t)(ii + 8 * (matI >> 1)) * 272u + (uint32_t)(matI & 1) * 16u;

    stage_chunk(sbase, 0, 0, t, gkb, gvb);
    CP_COMMIT();

    uint32_t qa0, qa1, qa2, qa3;
    {
        const float* gq = g_q + (size_t)b * 16 * N_PIX + n0;
        int nq = nw + g;
        qa0 = pkbf(gq[(2 * tig)     * N_PIX + nq],     gq[(2 * tig + 1) * N_PIX + nq]);
        qa1 = pkbf(gq[(2 * tig)     * N_PIX + nq + 8], gq[(2 * tig + 1) * N_PIX + nq + 8]);
        qa2 = pkbf(gq[(2 * tig + 8) * N_PIX + nq],     gq[(2 * tig + 9) * N_PIX + nq]);
        qa3 = pkbf(gq[(2 * tig + 8) * N_PIX + nq + 8], gq[(2 * tig + 9) * N_PIX + nq + 8]);
    }

    float oc[8][4];
#pragma unroll
    for (int i = 0; i < 8; i++)
#pragma unroll
        for (int j = 0; j < 4; j++) oc[i][j] = 0.f;
    float rs0 = 0.f, rs1 = 0.f;

#pragma unroll 1
    for (int chk = 0; chk < 8; chk++) {
        const int buf = chk & 1;

        CP_WAIT0();
        __syncthreads();

        if (chk < 7) {
            stage_chunk(sbase, buf ^ 1, chk + 1, t, gkb, gvb);
            CP_COMMIT();
        }

        const uint32_t kBase = sbase + SK_OFF(buf) * 4u + kOff;
        const uint32_t vBase = sbase + SV_OFF(buf) * 4u + vOff;

#pragma unroll
        for (int h = 0; h < 2; h++) {
            float sd[8][4];
#pragma unroll
            for (int j = 0; j < 8; j++)
#pragma unroll
                for (int k = 0; k < 4; k++) sd[j][k] = 0.f;

#pragma unroll
            for (int u = 0; u < 4; u++) {
                uint32_t k0, k1, k2, k3;
                LDMX4(k0, k1, k2, k3, kBase + (uint32_t)(4 * h + u) * 768u);
                MMA_BF16(sd[2 * u],     qa0, qa1, qa2, qa3, k0, k1);
                MMA_BF16(sd[2 * u + 1], qa0, qa1, qa2, qa3, k2, k3);
            }

            uint32_t pa[4][4];
#pragma unroll
            for (int j = 0; j < 4; j++) {
                uint32_t h00 = pkbf(__expf(sd[2 * j][0]),     __expf(sd[2 * j][1]));
                uint32_t h01 = pkbf(__expf(sd[2 * j][2]),     __expf(sd[2 * j][3]));
                uint32_t h10 = pkbf(__expf(sd[2 * j + 1][0]), __expf(sd[2 * j + 1][1]));
                uint32_t h11 = pkbf(__expf(sd[2 * j + 1][2]), __expf(sd[2 * j + 1][3]));
                rs0 += sum2bf(h00) + sum2bf(h10);
                rs1 += sum2bf(h01) + sum2bf(h11);
                pa[j][0] = h00; pa[j][1] = h01; pa[j][2] = h10; pa[j][3] = h11;
            }

#pragma unroll
            for (int kt = 0; kt < 4; kt++) {
                const uint32_t colb = (uint32_t)(4 * h + kt) * 32u;
#pragma unroll
                for (int cp = 0; cp < 4; cp++) {
                    uint32_t v0, v1, v2, v3;
                    LDMX4(v0, v1, v2, v3, vBase + (uint32_t)cp * 4352u + colb);
                    MMA_BF16(oc[2 * cp],     pa[kt][0], pa[kt][1], pa[kt][2], pa[kt][3], v0, v1);
                    MMA_BF16(oc[2 * cp + 1], pa[kt][0], pa[kt][1], pa[kt][2], pa[kt][3], v2, v3);
                }
            }
        }
    }
    __syncthreads();

    float* sO = sm + SO_OFF;
#pragma unroll
    for (int ct = 0; ct < 8; ct++) {
        int c = 8 * ct + 2 * tig;
        sO[c * 136 + nw + g]           = tf32r(oc[ct][0]);
        sO[(c + 1) * 136 + nw + g]     = tf32r(oc[ct][1]);
        sO[c * 136 + nw + g + 8]       = tf32r(oc[ct][2]);
        sO[(c + 1) * 136 + nw + g + 8] = tf32r(oc[ct][3]);
    }
    rs0 += __shfl_xor_sync(0xffffffffu, rs0, 1);
    rs0 += __shfl_xor_sync(0xffffffffu, rs0, 2);
    rs1 += __shfl_xor_sync(0xffffffffu, rs1, 1);
    rs1 += __shfl_xor_sync(0xffffffffu, rs1, 2);
    if (tig == 0) {
        sSum[nw + g]     = rs0;
        sSum[nw + g + 8] = rs1;
    }
    float* sWo = sm + SWO_OFF;
    for (int i = t; i < 8192; i += 256) {
        int o = i >> 6, c = i & 63;
        sWo[c * 136 + o] = tf32r(wo[i]);
    }
    __syncthreads();

    if (t < 128) sInv[t] = 1.f / sSum[t];
    __syncthreads();

    {
        const int o0 = w * 16;
        float od[16][4];
#pragma unroll
        for (int j = 0; j < 16; j++)
#pragma unroll
            for (int k = 0; k < 4; k++) od[j][k] = 0.f;

#pragma unroll
        for (int ks = 0; ks < 8; ks++) {
            uint32_t a0 = __float_as_uint(sWo[(8 * ks + tig)     * 136 + o0 + g]);
            uint32_t a1 = __float_as_uint(sWo[(8 * ks + tig)     * 136 + o0 + g + 8]);
            uint32_t a2 = __float_as_uint(sWo[(8 * ks + tig + 4) * 136 + o0 + g]);
            uint32_t a3 = __float_as_uint(sWo[(8 * ks + tig + 4) * 136 + o0 + g + 8]);
#pragma unroll
            for (int nt = 0; nt < 16; nt++) {
                uint32_t b0 = __float_as_uint(sO[(8 * ks + tig)     * 136 + 8 * nt + g]);
                uint32_t b1 = __float_as_uint(sO[(8 * ks + tig + 4) * 136 + 8 * nt + g]);
                MMA_TF32(od[nt], a0, a1, a2, a3, b0, b1);
            }
        }

        const float gm = gamma[0];
#pragma unroll
        for (int nt = 0; nt < 16; nt++) {
            int nn = 8 * nt + 2 * tig;
            float s0 = gm * sInv[nn];
            float s1 = gm * sInv[nn + 1];
            size_t gi0 = ((size_t)(b * 128 + o0 + g)) * N_PIX + n0 + nn;
            size_t gi1 = ((size_t)(b * 128 + o0 + g + 8)) * N_PIX + n0 + nn;
            float2 x0 = *(const float2*)&x[gi0];
            float2 x1 = *(const float2*)&x[gi1];
            float2 r0, r1;
            r0.x = fmaf(s0, od[nt][0], x0.x);
            r0.y = fmaf(s1, od[nt][1], x0.y);
            r1.x = fmaf(s0, od[nt][2], x1.x);
            r1.y = fmaf(s1, od[nt][3], x1.y);
            *(float2*)&out[gi0] = r0;
            *(float2*)&out[gi1] = r1;
        }
    }
}

// ---------------------------------------------------------------------------
extern "C" void kernel_launch(void* const* d_in, const int* in_sizes, int n_in,
                              void* d_out, int out_size)
{
    const float* x     = (const float*)d_in[0];
    const float* wq    = (const float*)d_in[1];
    const float* wk    = (const float*)d_in[2];
    const float* wv    = (const float*)d_in[3];
    const float* wo    = (const float*)d_in[4];
    const float* gamma = (const float*)d_in[5];
    float* out = (float*)d_out;

    const int smem1 = K1_SMEM * 4;        // 69632
    const int smem2 = SMEM2_FLOATS * 4;   // 70656

    cudaFuncSetAttribute(proj_pool_kernel, cudaFuncAttributeMaxDynamicSharedMemorySize, smem1);
    cudaFuncSetAttribute(attn_kernel,      cudaFuncAttributeMaxDynamicSharedMemorySize, smem2);

    proj_pool_kernel<<<dim3(32, 16), 256, smem1>>>(x, wq, wk, wv);
    attn_kernel<<<dim3(32, 16), 256, smem2>>>(x, wo, gamma, out);
}

// round 14
// speedup vs baseline: 6.1190x; 1.1649x over previous
#include <cuda_runtime.h>
#include <cuda_bf16.h>
#include <cstdint>

#define N_PIX 4096
#define M_PIX 1024

// cp.async helpers (16B per op)
#define CPA(dst32, srcp) \
    asm volatile("cp.async.ca.shared.global [%0], [%1], 16;" :: "r"(dst32), "l"(srcp) : "memory")
#define CP_COMMIT() asm volatile("cp.async.commit_group;" ::: "memory")
#define CP_WAIT0()  asm volatile("cp.async.wait_group 0;" ::: "memory")

// ldmatrix x4 (b16)
#define LDMX4(r0, r1, r2, r3, addr) \
    asm volatile("ldmatrix.sync.aligned.m8n8.x4.shared.b16 {%0,%1,%2,%3}, [%4];" \
        : "=r"(r0), "=r"(r1), "=r"(r2), "=r"(r3) : "r"(addr))
#define LDMX4T(r0, r1, r2, r3, addr) \
    asm volatile("ldmatrix.sync.aligned.m8n8.x4.trans.shared.b16 {%0,%1,%2,%3}, [%4];" \
        : "=r"(r0), "=r"(r1), "=r"(r2), "=r"(r3) : "r"(addr))

// m16n8k16 bf16 MMA, fp32 accumulate
#define MMA_BF16(d, a0, a1, a2, a3, b0, b1) \
    asm volatile("mma.sync.aligned.m16n8k16.row.col.f32.bf16.bf16.f32 " \
        "{%0,%1,%2,%3}, {%4,%5,%6,%7}, {%8,%9}, {%0,%1,%2,%3};" \
        : "+f"(d[0]), "+f"(d[1]), "+f"(d[2]), "+f"(d[3]) \
        : "r"(a0), "r"(a1), "r"(a2), "r"(a3), "r"(b0), "r"(b1))

// m16n8k8 tf32 MMA, fp32 accumulate
#define MMA_TF32(d, a0, a1, a2, a3, b0, b1) \
    asm volatile("mma.sync.aligned.m16n8k8.row.col.f32.tf32.tf32.f32 " \
        "{%0,%1,%2,%3}, {%4,%5,%6,%7}, {%8,%9}, {%0,%1,%2,%3};" \
        : "+f"(d[0]), "+f"(d[1]), "+f"(d[2]), "+f"(d[3]) \
        : "r"(a0), "r"(a1), "r"(a2), "r"(a3), "r"(b0), "r"(b1))

// tf32 round-to-nearest
__device__ __forceinline__ float tf32r(float f) {
    uint32_t u;
    asm("cvt.rna.tf32.f32 %0, %1;" : "=r"(u) : "f"(f));
    return __uint_as_float(u);
}
__device__ __forceinline__ uint32_t pkbf(float a, float b) {
    __nv_bfloat162 h = __float22bfloat162_rn(make_float2(a, b));
    return *reinterpret_cast<uint32_t*>(&h);
}
__device__ __forceinline__ float ex2f(float x) {
    float r;
    asm("ex2.approx.f32 %0, %1;" : "=f"(r) : "f"(x));
    return r;
}

// Scratch (device globals — no allocation allowed)
__device__ __align__(16) float         g_q[16 * 16 * N_PIX];   // [b][16][n] fp32
__device__ __align__(16) __nv_bfloat16 g_k[16 * M_PIX * 16];   // [b][m][16] bf16
__device__ __align__(16) __nv_bfloat16 g_v[16 * 64 * M_PIX];   // [b][64][m] bf16

// ---------------------------------------------------------------------------
// Kernel 1 (bf16-tensorized): out[96][128px] = W*x on bf16 MMA + ldmatrix,
// then 2x2 maxpool. x loaded LDG->CVT->STS bf16 directly (no fp32 staging),
// double-buffered; LDG of chunk kc+1 issued before the sync so MMA(kc) hides
// its latency. W staged once bf16 [o][c] stride 136.
// ---------------------------------------------------------------------------
#define K1_W    0        // bf16 96x136 = 6528 fl
#define K1_XB0  6528     // bf16 32x136 = 2176 fl
#define K1_XB1  8704     // bf16 32x136 = 2176 fl
#define K1_SMEM 10880    // floats = 43520 B

__global__ __launch_bounds__(256, 2) void proj_pool_kernel(
    const float* __restrict__ x,
    const float* __restrict__ wq,
    const float* __restrict__ wk,
    const float* __restrict__ wv)
{
    extern __shared__ float sm[];
    __nv_bfloat16* sWb = (__nv_bfloat16*)(sm + K1_W);     // [96][136]

    const int t    = threadIdx.x;
    const int lane = t & 31;
    const int w    = t >> 5;
    const int g    = lane >> 2;
    const int tig  = lane & 3;
    const int b    = blockIdx.y;
    const int px0  = blockIdx.x * 128;

    const float* xb = x + (size_t)b * 128 * N_PIX;
    const uint32_t sbase = (uint32_t)__cvta_generic_to_shared(sm);

    const int xr_row = t >> 3;             // 0..31 (channel within chunk)
    const int xr_col = (t & 7) * 4;        // float col base; +q*32

    // ---- LDG chunk 0 into registers ----
    float4 xr[4];
#pragma unroll
    for (int q = 0; q < 4; q++)
        xr[q] = *(const float4*)&xb[(size_t)xr_row * N_PIX + px0 + xr_col + q * 32];

    // ---- stage W bf16 [o][c] stride 136 (overlaps LDG latency) ----
    for (int i = t; i < 6144; i += 256) {
        int o = i >> 6, c2 = i & 63;
        const float* src = (o < 16) ? (wq + o * 128)
                         : (o < 32) ? (wk + (o - 16) * 128)
                                    : (wv + (o - 32) * 128);
        *(uint32_t*)(sWb + o * 136 + 2 * c2) = pkbf(src[2 * c2], src[2 * c2 + 1]);
    }

    float dd[6][8];
#pragma unroll
    for (int mt = 0; mt < 6; mt++)
#pragma unroll
        for (int j = 0; j < 8; j++) dd[mt][j] = 0.f;

    const int nA   = w * 16;
    const int matI = lane >> 3, ii = lane & 7;
    const uint32_t aOff = (uint32_t)(ii + 8 * (matI & 1)) * 272u + (uint32_t)(matI >> 1) * 16u;
    const uint32_t bOff = (uint32_t)(ii + 8 * (matI & 1)) * 272u + (uint32_t)(nA + 8 * (matI >> 1)) * 2u;

#pragma unroll 1
    for (int kc = 0; kc < 4; kc++) {
        const int buf = kc & 1;
        // ---- convert current regs -> bf16 smem ----
        {
            __nv_bfloat16* xbuf = (__nv_bfloat16*)(sm + (buf ? K1_XB1 : K1_XB0));
#pragma unroll
            for (int q = 0; q < 4; q++) {
                uint2 u;
                u.x = pkbf(xr[q].x, xr[q].y);
                u.y = pkbf(xr[q].z, xr[q].w);
                *(uint2*)(xbuf + xr_row * 136 + xr_col + q * 32) = u;
            }
        }
        // ---- prefetch next chunk (latency hidden by MMA below) ----
        if (kc < 3) {
#pragma unroll
            for (int q = 0; q < 4; q++)
                xr[q] = *(const float4*)&xb[(size_t)(kc * 32 + 32 + xr_row) * N_PIX
                                            + px0 + xr_col + q * 32];
        }
        __syncthreads();               // buf ready for all; prev-buf MMA done

        // ---- MMA: 2 k16-steps x 6 m-tiles x 2 n-tiles ----
        const uint32_t aB = sbase + aOff;
        const uint32_t bB = sbase + (uint32_t)(buf ? K1_XB1 : K1_XB0) * 4u + bOff;
#pragma unroll
        for (int ks = 0; ks < 2; ks++) {
            uint32_t x0, x1, x2, x3;
            LDMX4T(x0, x1, x2, x3, bB + (uint32_t)ks * 16u * 272u);
#pragma unroll
            for (int mt = 0; mt < 6; mt++) {
                uint32_t a0, a1, a2, a3;
                LDMX4(a0, a1, a2, a3, aB + (uint32_t)(mt * 16) * 272u
                                         + (uint32_t)(kc * 64 + ks * 32));
                MMA_BF16((&dd[mt][0]), a0, a1, a2, a3, x0, x1);
                MMA_BF16((&dd[mt][4]), a0, a1, a2, a3, x2, x3);
            }
        }
    }
    __syncthreads();                   // W + x buffers dead -> pool scratch

    // ---- q (m-tile 0): write fragments straight to gmem (fp32) ----
#pragma unroll
    for (int nb = 0; nb < 2; nb++) {
        int n = nA + nb * 8 + 2 * tig;
        size_t qi0 = ((size_t)(b * 16 + g))     * N_PIX + px0 + n;
        size_t qi1 = ((size_t)(b * 16 + g + 8)) * N_PIX + px0 + n;
        *(float2*)&g_q[qi0] = make_float2(dd[0][nb * 4],     dd[0][nb * 4 + 1]);
        *(float2*)&g_q[qi1] = make_float2(dd[0][nb * 4 + 2], dd[0][nb * 4 + 3]);
    }

    // ---- k/v: horizontal max intra-thread -> pool scratch (aliases W) ----
    float* pb = sm;                    // [80 ch][2 rows][34] = 5440 <= 6528
#pragma unroll
    for (int mt = 1; mt < 6; mt++) {
#pragma unroll
        for (int nb = 0; nb < 2; nb++) {
            int n = nA + nb * 8 + 2 * tig;
            int rrow = n >> 6;
            int wp = (n & 63) >> 1;
            int ch = mt * 16 - 16 + g;
            pb[ch * 68 + rrow * 34 + wp]       = fmaxf(dd[mt][nb * 4],     dd[mt][nb * 4 + 1]);
            pb[(ch + 8) * 68 + rrow * 34 + wp] = fmaxf(dd[mt][nb * 4 + 2], dd[mt][nb * 4 + 3]);
        }
    }
    __syncthreads();

    const int mbase = blockIdx.x * 32;
    for (int i = t; i < 2560; i += 256) {
        int ch = i >> 5, wp = i & 31;
        float r = fmaxf(pb[ch * 68 + wp], pb[ch * 68 + 34 + wp]);
        if (ch < 16)
            g_k[((size_t)(b * M_PIX + mbase + wp)) * 16 + ch] = __float2bfloat16_rn(r);
        else
            g_v[((b * 64 + ch - 16) << 10) + mbase + wp] = __float2bfloat16_rn(r);
    }
}

// ---------------------------------------------------------------------------
// Kernel 2: FA2-style fused attention. Q pre-scaled by log2(e) -> ex2 only;
// rowsums via ones-MMA on the tensor pipe (no scalar unpack/reduce).
// ---------------------------------------------------------------------------
#define SV_OFF(buf)  ((buf) ? 4352u : 0u)
#define SK_OFF(buf)  (8704u + ((buf) ? 1536u : 0u))
#define SO_OFF       0u
#define SWO_OFF      8704u
#define SSUM_OFF     17408u
#define SINV_OFF     17536u
#define SMEM2_FLOATS 17664

__device__ __forceinline__ void stage_chunk(
    uint32_t sbase, int buf, int chk, int t,
    const __nv_bfloat16* __restrict__ gkb, const __nv_bfloat16* __restrict__ gvb)
{
    uint32_t kdst = sbase + SK_OFF(buf) * 4u;
    uint32_t vdst = sbase + SV_OFF(buf) * 4u;
    {
        int m = t >> 1, h = t & 1;
        CPA(kdst + (uint32_t)m * 48u + (uint32_t)h * 16u,
            gkb + ((size_t)(chk * 128 + m)) * 16 + h * 8);
    }
#pragma unroll
    for (int q = 0; q < 4; q++) {
        int i = t + q * 256;
        int r = i >> 4, u = i & 15;
        CPA(vdst + (uint32_t)r * 272u + (uint32_t)u * 16u,
            gvb + ((size_t)r << 10) + chk * 128 + u * 8);
    }
}

__global__ __launch_bounds__(256, 2) void attn_kernel(
    const float* __restrict__ x,
    const float* __restrict__ wo,
    const float* __restrict__ gamma,
    float* __restrict__ out)
{
    extern __shared__ float sm[];
    float* sSum = sm + SSUM_OFF;
    float* sInv = sm + SINV_OFF;

    const int t    = threadIdx.x;
    const int w    = t >> 5;
    const int lane = t & 31;
    const int b    = blockIdx.y;
    const int n0   = blockIdx.x * 128;

    const int g    = lane >> 2;
    const int tig  = lane & 3;
    const int nw   = w * 16;
    const int matI = lane >> 3, ii = lane & 7;

    const uint32_t sbase = (uint32_t)__cvta_generic_to_shared(sm);
    const __nv_bfloat16* gkb = g_k + (size_t)b * M_PIX * 16;
    const __nv_bfloat16* gvb = g_v + (size_t)b * 64 * M_PIX;

    const uint32_t kOff = (uint32_t)(ii + 8 * (matI >> 1)) * 48u + (uint32_t)(matI & 1) * 16u;
    const uint32_t vOff = (uint32_t)(ii + 8 * (matI >> 1)) * 272u + (uint32_t)(matI & 1) * 16u;

    stage_chunk(sbase, 0, 0, t, gkb, gvb);
    CP_COMMIT();

    // Q fragments pre-scaled by log2(e): scores emerge in log2 domain.
    const float L2E = 1.44269504f;
    uint32_t qa0, qa1, qa2, qa3;
    {
        const float* gq = g_q + (size_t)b * 16 * N_PIX + n0;
        int nq = nw + g;
        qa0 = pkbf(gq[(2 * tig)     * N_PIX + nq]     * L2E, gq[(2 * tig + 1) * N_PIX + nq]     * L2E);
        qa1 = pkbf(gq[(2 * tig)     * N_PIX + nq + 8] * L2E, gq[(2 * tig + 1) * N_PIX + nq + 8] * L2E);
        qa2 = pkbf(gq[(2 * tig + 8) * N_PIX + nq]     * L2E, gq[(2 * tig + 9) * N_PIX + nq]     * L2E);
        qa3 = pkbf(gq[(2 * tig + 8) * N_PIX + nq + 8] * L2E, gq[(2 * tig + 9) * N_PIX + nq + 8] * L2E);
    }

    float oc[8][4];
#pragma unroll
    for (int i = 0; i < 8; i++)
#pragma unroll
        for (int j = 0; j < 4; j++) oc[i][j] = 0.f;
    float rsd[4] = {0.f, 0.f, 0.f, 0.f};     // rowsum accumulator (ones-MMA)
    const uint32_t ONE2 = 0x3F803F80u;        // bf16x2 {1.0, 1.0}

#pragma unroll 1
    for (int chk = 0; chk < 8; chk++) {
        const int buf = chk & 1;

        CP_WAIT0();
        __syncthreads();

        if (chk < 7) {
            stage_chunk(sbase, buf ^ 1, chk + 1, t, gkb, gvb);
            CP_COMMIT();
        }

        const uint32_t kBase = sbase + SK_OFF(buf) * 4u + kOff;
        const uint32_t vBase = sbase + SV_OFF(buf) * 4u + vOff;

#pragma unroll
        for (int h = 0; h < 2; h++) {
            float sd[8][4];
#pragma unroll
            for (int j = 0; j < 8; j++)
#pragma unroll
                for (int k = 0; k < 4; k++) sd[j][k] = 0.f;

#pragma unroll
            for (int u = 0; u < 4; u++) {
                uint32_t k0, k1, k2, k3;
                LDMX4(k0, k1, k2, k3, kBase + (uint32_t)(4 * h + u) * 768u);
                MMA_BF16(sd[2 * u],     qa0, qa1, qa2, qa3, k0, k1);
                MMA_BF16(sd[2 * u + 1], qa0, qa1, qa2, qa3, k2, k3);
            }

            // exp2 + bf16 pack; rowsum via ones-MMA (tensor pipe)
            uint32_t pa[4][4];
#pragma unroll
            for (int j = 0; j < 4; j++) {
                pa[j][0] = pkbf(ex2f(sd[2 * j][0]),     ex2f(sd[2 * j][1]));
                pa[j][1] = pkbf(ex2f(sd[2 * j][2]),     ex2f(sd[2 * j][3]));
                pa[j][2] = pkbf(ex2f(sd[2 * j + 1][0]), ex2f(sd[2 * j + 1][1]));
                pa[j][3] = pkbf(ex2f(sd[2 * j + 1][2]), ex2f(sd[2 * j + 1][3]));
                MMA_BF16(rsd, pa[j][0], pa[j][1], pa[j][2], pa[j][3], ONE2, ONE2);
            }

#pragma unroll
            for (int kt = 0; kt < 4; kt++) {
                const uint32_t colb = (uint32_t)(4 * h + kt) * 32u;
#pragma unroll
                for (int cp = 0; cp < 4; cp++) {
                    uint32_t v0, v1, v2, v3;
                    LDMX4(v0, v1, v2, v3, vBase + (uint32_t)cp * 4352u + colb);
                    MMA_BF16(oc[2 * cp],     pa[kt][0], pa[kt][1], pa[kt][2], pa[kt][3], v0, v1);
                    MMA_BF16(oc[2 * cp + 1], pa[kt][0], pa[kt][1], pa[kt][2], pa[kt][3], v2, v3);
                }
            }
        }
    }
    __syncthreads();

    float* sO = sm + SO_OFF;
#pragma unroll
    for (int ct = 0; ct < 8; ct++) {
        int c = 8 * ct + 2 * tig;
        sO[c * 136 + nw + g]           = tf32r(oc[ct][0]);
        sO[(c + 1) * 136 + nw + g]     = tf32r(oc[ct][1]);
        sO[c * 136 + nw + g + 8]       = tf32r(oc[ct][2]);
        sO[(c + 1) * 136 + nw + g + 8] = tf32r(oc[ct][3]);
    }
    // rowsums: every column of the ones-MMA D is the full rowsum already
    if (tig == 0) {
        sSum[nw + g]     = rsd[0];
        sSum[nw + g + 8] = rsd[2];
    }
    float* sWo = sm + SWO_OFF;
    for (int i = t; i < 8192; i += 256) {
        int o = i >> 6, c = i & 63;
        sWo[c * 136 + o] = tf32r(wo[i]);
    }
    __syncthreads();

    if (t < 128) sInv[t] = 1.f / sSum[t];
    __syncthreads();

    {
        const int o0 = w * 16;
        float od[16][4];
#pragma unroll
        for (int j = 0; j < 16; j++)
#pragma unroll
            for (int k = 0; k < 4; k++) od[j][k] = 0.f;

#pragma unroll
        for (int ks = 0; ks < 8; ks++) {
            uint32_t a0 = __float_as_uint(sWo[(8 * ks + tig)     * 136 + o0 + g]);
            uint32_t a1 = __float_as_uint(sWo[(8 * ks + tig)     * 136 + o0 + g + 8]);
            uint32_t a2 = __float_as_uint(sWo[(8 * ks + tig + 4) * 136 + o0 + g]);
            uint32_t a3 = __float_as_uint(sWo[(8 * ks + tig + 4) * 136 + o0 + g + 8]);
#pragma unroll
            for (int nt = 0; nt < 16; nt++) {
                uint32_t b0 = __float_as_uint(sO[(8 * ks + tig)     * 136 + 8 * nt + g]);
                uint32_t b1 = __float_as_uint(sO[(8 * ks + tig + 4) * 136 + 8 * nt + g]);
                MMA_TF32(od[nt], a0, a1, a2, a3, b0, b1);
            }
        }

        const float gm = gamma[0];
#pragma unroll
        for (int nt = 0; nt < 16; nt++) {
            int nn = 8 * nt + 2 * tig;
            float s0 = gm * sInv[nn];
            float s1 = gm * sInv[nn + 1];
            size_t gi0 = ((size_t)(b * 128 + o0 + g)) * N_PIX + n0 + nn;
            size_t gi1 = ((size_t)(b * 128 + o0 + g + 8)) * N_PIX + n0 + nn;
            float2 x0 = *(const float2*)&x[gi0];
            float2 x1 = *(const float2*)&x[gi1];
            float2 r0, r1;
            r0.x = fmaf(s0, od[nt][0], x0.x);
            r0.y = fmaf(s1, od[nt][1], x0.y);
            r1.x = fmaf(s0, od[nt][2], x1.x);
            r1.y = fmaf(s1, od[nt][3], x1.y);
            *(float2*)&out[gi0] = r0;
            *(float2*)&out[gi1] = r1;
        }
    }
}

// ---------------------------------------------------------------------------
extern "C" void kernel_launch(void* const* d_in, const int* in_sizes, int n_in,
                              void* d_out, int out_size)
{
    const float* x     = (const float*)d_in[0];
    const float* wq    = (const float*)d_in[1];
    const float* wk    = (const float*)d_in[2];
    const float* wv    = (const float*)d_in[3];
    const float* wo    = (const float*)d_in[4];
    const float* gamma = (const float*)d_in[5];
    float* out = (float*)d_out;

    const int smem1 = K1_SMEM * 4;        // 43520
    const int smem2 = SMEM2_FLOATS * 4;   // 70656

    cudaFuncSetAttribute(proj_pool_kernel, cudaFuncAttributeMaxDynamicSharedMemorySize, smem1);
    cudaFuncSetAttribute(attn_kernel,      cudaFuncAttributeMaxDynamicSharedMemorySize, smem2);

    proj_pool_kernel<<<dim3(32, 16), 256, smem1>>>(x, wq, wk, wv);
    attn_kernel<<<dim3(32, 16), 256, smem2>>>(x, wo, gamma, out);
}

// round 15
// speedup vs baseline: 6.3883x; 1.0440x over previous
#include <cuda_runtime.h>
#include <cuda_bf16.h>
#include <cstdint>

#define N_PIX 4096
#define M_PIX 1024

// cp.async helpers (16B per op)
#define CPA(dst32, srcp) \
    asm volatile("cp.async.ca.shared.global [%0], [%1], 16;" :: "r"(dst32), "l"(srcp) : "memory")
#define CP_COMMIT() asm volatile("cp.async.commit_group;" ::: "memory")
#define CP_WAIT0()  asm volatile("cp.async.wait_group 0;" ::: "memory")

// ldmatrix x4 (b16)
#define LDMX4(r0, r1, r2, r3, addr) \
    asm volatile("ldmatrix.sync.aligned.m8n8.x4.shared.b16 {%0,%1,%2,%3}, [%4];" \
        : "=r"(r0), "=r"(r1), "=r"(r2), "=r"(r3) : "r"(addr))
#define LDMX4T(r0, r1, r2, r3, addr) \
    asm volatile("ldmatrix.sync.aligned.m8n8.x4.trans.shared.b16 {%0,%1,%2,%3}, [%4];" \
        : "=r"(r0), "=r"(r1), "=r"(r2), "=r"(r3) : "r"(addr))

// m16n8k16 bf16 MMA, fp32 accumulate
#define MMA_BF16(d, a0, a1, a2, a3, b0, b1) \
    asm volatile("mma.sync.aligned.m16n8k16.row.col.f32.bf16.bf16.f32 " \
        "{%0,%1,%2,%3}, {%4,%5,%6,%7}, {%8,%9}, {%0,%1,%2,%3};" \
        : "+f"(d[0]), "+f"(d[1]), "+f"(d[2]), "+f"(d[3]) \
        : "r"(a0), "r"(a1), "r"(a2), "r"(a3), "r"(b0), "r"(b1))

__device__ __forceinline__ uint32_t pkbf(float a, float b) {
    __nv_bfloat162 h = __float22bfloat162_rn(make_float2(a, b));
    return *reinterpret_cast<uint32_t*>(&h);
}
__device__ __forceinline__ float ex2f(float x) {
    float r;
    asm("ex2.approx.f32 %0, %1;" : "=f"(r) : "f"(x));
    return r;
}

// Scratch (device globals — no allocation allowed)
__device__ __align__(16) __nv_bfloat16 g_q[16 * 16 * N_PIX];   // [b][16][n] bf16, pre-scaled log2(e)
__device__ __align__(16) __nv_bfloat16 g_k[16 * M_PIX * 16];   // [b][m][16] bf16
__device__ __align__(16) __nv_bfloat16 g_v[16 * 64 * M_PIX];   // [b][64][m] bf16

// ---------------------------------------------------------------------------
// Kernel 1 (bf16-tensorized): out[96][128px] = W*x on bf16 MMA + ldmatrix,
// then 2x2 maxpool. x loaded LDG->CVT->STS bf16 directly, double-buffered.
// q stored bf16 pre-scaled by log2(e).
// ---------------------------------------------------------------------------
#define K1_W    0        // bf16 96x136 = 6528 fl
#define K1_XB0  6528     // bf16 32x136 = 2176 fl
#define K1_XB1  8704     // bf16 32x136 = 2176 fl
#define K1_SMEM 10880    // floats = 43520 B

__global__ __launch_bounds__(256, 2) void proj_pool_kernel(
    const float* __restrict__ x,
    const float* __restrict__ wq,
    const float* __restrict__ wk,
    const float* __restrict__ wv)
{
    extern __shared__ float sm[];
    __nv_bfloat16* sWb = (__nv_bfloat16*)(sm + K1_W);     // [96][136]

    const int t    = threadIdx.x;
    const int lane = t & 31;
    const int w    = t >> 5;
    const int g    = lane >> 2;
    const int tig  = lane & 3;
    const int b    = blockIdx.y;
    const int px0  = blockIdx.x * 128;

    const float* xb = x + (size_t)b * 128 * N_PIX;
    const uint32_t sbase = (uint32_t)__cvta_generic_to_shared(sm);

    const int xr_row = t >> 3;
    const int xr_col = (t & 7) * 4;

    float4 xr[4];
#pragma unroll
    for (int q = 0; q < 4; q++)
        xr[q] = *(const float4*)&xb[(size_t)xr_row * N_PIX + px0 + xr_col + q * 32];

    for (int i = t; i < 6144; i += 256) {
        int o = i >> 6, c2 = i & 63;
        const float* src = (o < 16) ? (wq + o * 128)
                         : (o < 32) ? (wk + (o - 16) * 128)
                                    : (wv + (o - 32) * 128);
        *(uint32_t*)(sWb + o * 136 + 2 * c2) = pkbf(src[2 * c2], src[2 * c2 + 1]);
    }

    float dd[6][8];
#pragma unroll
    for (int mt = 0; mt < 6; mt++)
#pragma unroll
        for (int j = 0; j < 8; j++) dd[mt][j] = 0.f;

    const int nA   = w * 16;
    const int matI = lane >> 3, ii = lane & 7;
    const uint32_t aOff = (uint32_t)(ii + 8 * (matI & 1)) * 272u + (uint32_t)(matI >> 1) * 16u;
    const uint32_t bOff = (uint32_t)(ii + 8 * (matI & 1)) * 272u + (uint32_t)(nA + 8 * (matI >> 1)) * 2u;

#pragma unroll 1
    for (int kc = 0; kc < 4; kc++) {
        const int buf = kc & 1;
        {
            __nv_bfloat16* xbuf = (__nv_bfloat16*)(sm + (buf ? K1_XB1 : K1_XB0));
#pragma unroll
            for (int q = 0; q < 4; q++) {
                uint2 u;
                u.x = pkbf(xr[q].x, xr[q].y);
                u.y = pkbf(xr[q].z, xr[q].w);
                *(uint2*)(xbuf + xr_row * 136 + xr_col + q * 32) = u;
            }
        }
        if (kc < 3) {
#pragma unroll
            for (int q = 0; q < 4; q++)
                xr[q] = *(const float4*)&xb[(size_t)(kc * 32 + 32 + xr_row) * N_PIX
                                            + px0 + xr_col + q * 32];
        }
        __syncthreads();

        const uint32_t aB = sbase + aOff;
        const uint32_t bB = sbase + (uint32_t)(buf ? K1_XB1 : K1_XB0) * 4u + bOff;
#pragma unroll
        for (int ks = 0; ks < 2; ks++) {
            uint32_t x0, x1, x2, x3;
            LDMX4T(x0, x1, x2, x3, bB + (uint32_t)ks * 16u * 272u);
#pragma unroll
            for (int mt = 0; mt < 6; mt++) {
                uint32_t a0, a1, a2, a3;
                LDMX4(a0, a1, a2, a3, aB + (uint32_t)(mt * 16) * 272u
                                         + (uint32_t)(kc * 64 + ks * 32));
                MMA_BF16((&dd[mt][0]), a0, a1, a2, a3, x0, x1);
                MMA_BF16((&dd[mt][4]), a0, a1, a2, a3, x2, x3);
            }
        }
    }
    __syncthreads();

    // ---- q: bf16, pre-scaled by log2(e), n-adjacent pairs -> u32 stores ----
    const float L2E = 1.44269504f;
#pragma unroll
    for (int nb = 0; nb < 2; nb++) {
        int n = nA + nb * 8 + 2 * tig;
        size_t qi0 = ((size_t)(b * 16 + g))     * N_PIX + px0 + n;
        size_t qi1 = ((size_t)(b * 16 + g + 8)) * N_PIX + px0 + n;
        *(uint32_t*)&g_q[qi0] = pkbf(dd[0][nb * 4]     * L2E, dd[0][nb * 4 + 1] * L2E);
        *(uint32_t*)&g_q[qi1] = pkbf(dd[0][nb * 4 + 2] * L2E, dd[0][nb * 4 + 3] * L2E);
    }

    // ---- k/v: horizontal max intra-thread -> pool scratch (aliases W) ----
    float* pb = sm;
#pragma unroll
    for (int mt = 1; mt < 6; mt++) {
#pragma unroll
        for (int nb = 0; nb < 2; nb++) {
            int n = nA + nb * 8 + 2 * tig;
            int rrow = n >> 6;
            int wp = (n & 63) >> 1;
            int ch = mt * 16 - 16 + g;
            pb[ch * 68 + rrow * 34 + wp]       = fmaxf(dd[mt][nb * 4],     dd[mt][nb * 4 + 1]);
            pb[(ch + 8) * 68 + rrow * 34 + wp] = fmaxf(dd[mt][nb * 4 + 2], dd[mt][nb * 4 + 3]);
        }
    }
    __syncthreads();

    const int mbase = blockIdx.x * 32;
    for (int i = t; i < 2560; i += 256) {
        int ch = i >> 5, wp = i & 31;
        float r = fmaxf(pb[ch * 68 + wp], pb[ch * 68 + 34 + wp]);
        if (ch < 16)
            g_k[((size_t)(b * M_PIX + mbase + wp)) * 16 + ch] = __float2bfloat16_rn(r);
        else
            g_v[((b * 64 + ch - 16) << 10) + mbase + wp] = __float2bfloat16_rn(r);
    }
}

// ---------------------------------------------------------------------------
// Kernel 2: FA2-style fused attention; all-bf16 (S, O, epilogue on tensor
// pipe; rowsums via ones-MMA). Epilogue: sO bf16 [n][72c], sWo bf16 [o][72c],
// straight ldmatrix operands.
// ---------------------------------------------------------------------------
#define SV_OFF(buf)  ((buf) ? 4352u : 0u)
#define SK_OFF(buf)  (8704u + ((buf) ? 1536u : 0u))
#define SO_OFF       0u      // bf16 [128][72] = 4608 fl
#define SWO_OFF      4608u   // bf16 [128][72] = 4608 fl
#define SSUM_OFF     17408u
#define SINV_OFF     17536u
#define SMEM2_FLOATS 17664

__device__ __forceinline__ void stage_chunk(
    uint32_t sbase, int buf, int chk, int t,
    const __nv_bfloat16* __restrict__ gkb, const __nv_bfloat16* __restrict__ gvb)
{
    uint32_t kdst = sbase + SK_OFF(buf) * 4u;
    uint32_t vdst = sbase + SV_OFF(buf) * 4u;
    {
        int m = t >> 1, h = t & 1;
        CPA(kdst + (uint32_t)m * 48u + (uint32_t)h * 16u,
            gkb + ((size_t)(chk * 128 + m)) * 16 + h * 8);
    }
#pragma unroll
    for (int q = 0; q < 4; q++) {
        int i = t + q * 256;
        int r = i >> 4, u = i & 15;
        CPA(vdst + (uint32_t)r * 272u + (uint32_t)u * 16u,
            gvb + ((size_t)r << 10) + chk * 128 + u * 8);
    }
}

__global__ __launch_bounds__(256, 2) void attn_kernel(
    const float* __restrict__ x,
    const float* __restrict__ wo,
    const float* __restrict__ gamma,
    float* __restrict__ out)
{
    extern __shared__ float sm[];
    float* sSum = sm + SSUM_OFF;
    float* sInv = sm + SINV_OFF;

    const int t    = threadIdx.x;
    const int w    = t >> 5;
    const int lane = t & 31;
    const int b    = blockIdx.y;
    const int n0   = blockIdx.x * 128;

    const int g    = lane >> 2;
    const int tig  = lane & 3;
    const int nw   = w * 16;
    const int matI = lane >> 3, ii = lane & 7;

    const uint32_t sbase = (uint32_t)__cvta_generic_to_shared(sm);
    const __nv_bfloat16* gkb = g_k + (size_t)b * M_PIX * 16;
    const __nv_bfloat16* gvb = g_v + (size_t)b * 64 * M_PIX;

    const uint32_t kOff = (uint32_t)(ii + 8 * (matI >> 1)) * 48u + (uint32_t)(matI & 1) * 16u;
    const uint32_t vOff = (uint32_t)(ii + 8 * (matI >> 1)) * 272u + (uint32_t)(matI & 1) * 16u;

    stage_chunk(sbase, 0, 0, t, gkb, gvb);
    CP_COMMIT();

    // Q fragments: bf16 loads (pre-scaled by log2(e) in k1)
    uint32_t qa0, qa1, qa2, qa3;
    {
        const __nv_bfloat16* gq = g_q + (size_t)b * 16 * N_PIX + n0;
        const int nq = nw + g;
#define QLD(d, n) ((uint32_t)*(const unsigned short*)&gq[(size_t)(d) * N_PIX + (n)])
        qa0 = QLD(2 * tig, nq)         | (QLD(2 * tig + 1, nq)     << 16);
        qa1 = QLD(2 * tig, nq + 8)     | (QLD(2 * tig + 1, nq + 8) << 16);
        qa2 = QLD(2 * tig + 8, nq)     | (QLD(2 * tig + 9, nq)     << 16);
        qa3 = QLD(2 * tig + 8, nq + 8) | (QLD(2 * tig + 9, nq + 8) << 16);
#undef QLD
    }

    float oc[8][4];
#pragma unroll
    for (int i = 0; i < 8; i++)
#pragma unroll
        for (int j = 0; j < 4; j++) oc[i][j] = 0.f;
    float rsd[4] = {0.f, 0.f, 0.f, 0.f};
    const uint32_t ONE2 = 0x3F803F80u;

#pragma unroll 1
    for (int chk = 0; chk < 8; chk++) {
        const int buf = chk & 1;

        CP_WAIT0();
        __syncthreads();

        if (chk < 7) {
            stage_chunk(sbase, buf ^ 1, chk + 1, t, gkb, gvb);
            CP_COMMIT();
        }

        const uint32_t kBase = sbase + SK_OFF(buf) * 4u + kOff;
        const uint32_t vBase = sbase + SV_OFF(buf) * 4u + vOff;

#pragma unroll
        for (int h = 0; h < 2; h++) {
            float sd[8][4];
#pragma unroll
            for (int j = 0; j < 8; j++)
#pragma unroll
                for (int k = 0; k < 4; k++) sd[j][k] = 0.f;

#pragma unroll
            for (int u = 0; u < 4; u++) {
                uint32_t k0, k1, k2, k3;
                LDMX4(k0, k1, k2, k3, kBase + (uint32_t)(4 * h + u) * 768u);
                MMA_BF16(sd[2 * u],     qa0, qa1, qa2, qa3, k0, k1);
                MMA_BF16(sd[2 * u + 1], qa0, qa1, qa2, qa3, k2, k3);
            }

            uint32_t pa[4][4];
#pragma unroll
            for (int j = 0; j < 4; j++) {
                pa[j][0] = pkbf(ex2f(sd[2 * j][0]),     ex2f(sd[2 * j][1]));
                pa[j][1] = pkbf(ex2f(sd[2 * j][2]),     ex2f(sd[2 * j][3]));
                pa[j][2] = pkbf(ex2f(sd[2 * j + 1][0]), ex2f(sd[2 * j + 1][1]));
                pa[j][3] = pkbf(ex2f(sd[2 * j + 1][2]), ex2f(sd[2 * j + 1][3]));
                MMA_BF16(rsd, pa[j][0], pa[j][1], pa[j][2], pa[j][3], ONE2, ONE2);
            }

#pragma unroll
            for (int kt = 0; kt < 4; kt++) {
                const uint32_t colb = (uint32_t)(4 * h + kt) * 32u;
#pragma unroll
                for (int cp = 0; cp < 4; cp++) {
                    uint32_t v0, v1, v2, v3;
                    LDMX4(v0, v1, v2, v3, vBase + (uint32_t)cp * 4352u + colb);
                    MMA_BF16(oc[2 * cp],     pa[kt][0], pa[kt][1], pa[kt][2], pa[kt][3], v0, v1);
                    MMA_BF16(oc[2 * cp + 1], pa[kt][0], pa[kt][1], pa[kt][2], pa[kt][3], v2, v3);
                }
            }
        }
    }
    __syncthreads();   // all smem reads done; alias to epilogue layout

    // ---- O fragments -> sO bf16 [n][72c] (c-pairs adjacent -> u32 stores) ----
    __nv_bfloat16* sO = (__nv_bfloat16*)(sm + SO_OFF);
#pragma unroll
    for (int ct = 0; ct < 8; ct++) {
        int c = 8 * ct + 2 * tig;
        *(uint32_t*)&sO[(nw + g) * 72 + c]     = pkbf(oc[ct][0], oc[ct][1]);
        *(uint32_t*)&sO[(nw + g + 8) * 72 + c] = pkbf(oc[ct][2], oc[ct][3]);
    }
    // rowsums: every column of the ones-MMA D is the full rowsum
    if (tig == 0) {
        sSum[nw + g]     = rsd[0];
        sSum[nw + g + 8] = rsd[2];
    }
    // ---- wo -> sWo bf16 [o][72c] ----
    __nv_bfloat16* sWo = (__nv_bfloat16*)(sm + SWO_OFF);
    for (int i = t; i < 4096; i += 256) {
        int o = i >> 5, c2 = i & 31;
        *(uint32_t*)&sWo[o * 72 + 2 * c2] = pkbf(wo[o * 64 + 2 * c2], wo[o * 64 + 2 * c2 + 1]);
    }
    __syncthreads();

    if (t < 128) sInv[t] = 1.f / sSum[t];
    __syncthreads();

    // ---- epilogue on bf16 MMA: out[o][n] = gamma*inv[n]*(wo.O)[o][n] + x ----
    {
        const int o0 = w * 16;
        const uint32_t aE = sbase + SWO_OFF * 4u
            + (uint32_t)(o0 + ii + 8 * (matI & 1)) * 144u + (uint32_t)(matI >> 1) * 16u;
        const uint32_t bE = sbase + SO_OFF * 4u
            + (uint32_t)(ii + 8 * (matI >> 1)) * 144u + (uint32_t)(matI & 1) * 16u;

        float od[16][4];
#pragma unroll
        for (int j = 0; j < 16; j++)
#pragma unroll
            for (int k = 0; k < 4; k++) od[j][k] = 0.f;

#pragma unroll
        for (int ks = 0; ks < 4; ks++) {       // k = c, 4 x k16
            uint32_t a0, a1, a2, a3;
            LDMX4(a0, a1, a2, a3, aE + (uint32_t)ks * 32u);
#pragma unroll
            for (int nt2 = 0; nt2 < 8; nt2++) {
                uint32_t b0, b1, b2, b3;
                LDMX4(b0, b1, b2, b3, bE + (uint32_t)nt2 * 16u * 144u + (uint32_t)ks * 32u);
                MMA_BF16(od[2 * nt2],     a0, a1, a2, a3, b0, b1);
                MMA_BF16(od[2 * nt2 + 1], a0, a1, a2, a3, b2, b3);
            }
        }

        const float gm = gamma[0];
#pragma unroll
        for (int nt = 0; nt < 16; nt++) {
            int nn = 8 * nt + 2 * tig;
            float s0 = gm * sInv[nn];
            float s1 = gm * sInv[nn + 1];
            size_t gi0 = ((size_t)(b * 128 + o0 + g)) * N_PIX + n0 + nn;
            size_t gi1 = ((size_t)(b * 128 + o0 + g + 8)) * N_PIX + n0 + nn;
            float2 x0 = *(const float2*)&x[gi0];
            float2 x1 = *(const float2*)&x[gi1];
            float2 r0, r1;
            r0.x = fmaf(s0, od[nt][0], x0.x);
            r0.y = fmaf(s1, od[nt][1], x0.y);
            r1.x = fmaf(s0, od[nt][2], x1.x);
            r1.y = fmaf(s1, od[nt][3], x1.y);
            *(float2*)&out[gi0] = r0;
            *(float2*)&out[gi1] = r1;
        }
    }
}

// ---------------------------------------------------------------------------
extern "C" void kernel_launch(void* const* d_in, const int* in_sizes, int n_in,
                              void* d_out, int out_size)
{
    const float* x     = (const float*)d_in[0];
    const float* wq    = (const float*)d_in[1];
    const float* wk    = (const float*)d_in[2];
    const float* wv    = (const float*)d_in[3];
    const float* wo    = (const float*)d_in[4];
    const float* gamma = (const float*)d_in[5];
    float* out = (float*)d_out;

    const int smem1 = K1_SMEM * 4;        // 43520
    const int smem2 = SMEM2_FLOATS * 4;   // 70656

    cudaFuncSetAttribute(proj_pool_kernel, cudaFuncAttributeMaxDynamicSharedMemorySize, smem1);
    cudaFuncSetAttribute(attn_kernel,      cudaFuncAttributeMaxDynamicSharedMemorySize, smem2);

    proj_pool_kernel<<<dim3(32, 16), 256, smem1>>>(x, wq, wk, wv);
    attn_kernel<<<dim3(32, 16), 256, smem2>>>(x, wo, gamma, out);
}